// round 13
// baseline (speedup 1.0000x reference)
#include <cuda_runtime.h>
#include <cuda_bf16.h>
#include <cstdint>
#include <cstddef>

#define CUR   512
#define FULL  1024
#define BS    4
#define DIMM  1024
#define NH    16
#define HD    64
#define PREV  512

typedef __nv_bfloat16 bf;

// ---------------- scratch (bf16 hi/lo pairs + fp32 C2) ----------------
__device__ __align__(256) bf g_FIh[4194304], g_FIl[4194304];     // full_input
__device__ __align__(256) bf g_INh[2097152], g_INl[2097152];     // inputs
__device__ __align__(256) bf g_PEh[1048576], g_PEl[1048576];     // pos_embedding
__device__ __align__(256) bf g_Wkvh[2097152], g_Wkvl[2097152];
__device__ __align__(256) bf g_Wqh[1048576],  g_Wql[1048576];
__device__ __align__(256) bf g_Wph[1048576],  g_Wpl[1048576];
__device__ __align__(256) bf g_Wprh[1048576], g_Wprl[1048576];
__device__ __align__(256) bf g_KVh[8388608],  g_KVl[8388608];    // (4096,2048) K|V
__device__ __align__(256) bf g_Quh[2097152],  g_Qul[2097152];    // 0.125*(Q+u)
__device__ __align__(256) bf g_Qvh[2097152],  g_Qvl[2097152];    // 0.125*(Q+v)
__device__ __align__(256) bf g_Rh[1048576],   g_Rl[1048576];
__device__ __align__(256) bf g_AVh[2097152],  g_AVl[2097152];
__device__ float g_C2[(size_t)BS * NH * CUR * FULL];

// ---------------- helpers ----------------
__device__ __forceinline__ uint32_t smem_u32(const void* p) {
    return (uint32_t)__cvta_generic_to_shared(p);
}
__device__ __forceinline__ void ldsm4(uint32_t* r, uint32_t a) {
    asm volatile("ldmatrix.sync.aligned.m8n8.x4.shared.b16 {%0,%1,%2,%3}, [%4];"
        : "=r"(r[0]), "=r"(r[1]), "=r"(r[2]), "=r"(r[3]) : "r"(a));
}
__device__ __forceinline__ void ldsm4t(uint32_t* r, uint32_t a) {
    asm volatile("ldmatrix.sync.aligned.m8n8.x4.trans.shared.b16 {%0,%1,%2,%3}, [%4];"
        : "=r"(r[0]), "=r"(r[1]), "=r"(r[2]), "=r"(r[3]) : "r"(a));
}
__device__ __forceinline__ void mmabf(float* d, const uint32_t* a, const uint32_t* b) {
    asm volatile(
        "mma.sync.aligned.m16n8k16.row.col.f32.bf16.bf16.f32 "
        "{%0,%1,%2,%3},{%4,%5,%6,%7},{%8,%9},{%0,%1,%2,%3};"
        : "+f"(d[0]), "+f"(d[1]), "+f"(d[2]), "+f"(d[3])
        : "r"(a[0]), "r"(a[1]), "r"(a[2]), "r"(a[3]), "r"(b[0]), "r"(b[1]));
}
__device__ __forceinline__ void store_split(bf* ph, bf* pl, float x, float y) {
    bf hx = __float2bfloat16(x), hy = __float2bfloat16(y);
    __nv_bfloat162 H; H.x = hx; H.y = hy;
    __nv_bfloat162 L;
    L.x = __float2bfloat16(x - __bfloat162float(hx));
    L.y = __float2bfloat16(y - __bfloat162float(hy));
    *(__nv_bfloat162*)ph = H;
    *(__nv_bfloat162*)pl = L;
}
__device__ __forceinline__ void split2(float x, float y, uint32_t& h, uint32_t& l) {
    bf hx = __float2bfloat16(x), hy = __float2bfloat16(y);
    __nv_bfloat162 H; H.x = hx; H.y = hy;
    __nv_bfloat162 L;
    L.x = __float2bfloat16(x - __bfloat162float(hx));
    L.y = __float2bfloat16(y - __bfloat162float(hy));
    h = *reinterpret_cast<uint32_t*>(&H);
    l = *reinterpret_cast<uint32_t*>(&L);
}
#define CPA(dst, src) \
    asm volatile("cp.async.cg.shared.global [%0], [%1], 16;" :: "r"(dst), "l"(src))
#define CPC() asm volatile("cp.async.commit_group;" ::: "memory")
#define CPW(n) asm volatile("cp.async.wait_group %0;" :: "n"(n) : "memory")
__device__ __forceinline__ void cpw_rem(int rem) {
    if (rem >= 2) CPW(2);
    else if (rem == 1) CPW(1);
    else CPW(0);
}

// ---------------- merged converter ----------------
struct CT {
    const float* s[7];
    bf* h[7];
    bf* l[7];
    int end[7];
};
__global__ __launch_bounds__(256)
void cvt_mega(CT c)
{
    const int bid = blockIdx.x;
    int ti = 0;
    #pragma unroll
    for (int k = 0; k < 6; k++) ti += (bid >= c.end[k]) ? 1 : 0;
    const int base = ti ? c.end[ti - 1] : 0;
    const int i = ((bid - base) * 256 + threadIdx.x) * 4;
    const float* x = c.s[ti];
    float4 v = *(const float4*)&x[i];
    store_split(&c.h[ti][i],     &c.l[ti][i],     v.x, v.y);
    store_split(&c.h[ti][i + 2], &c.l[ti][i + 2], v.z, v.w);
}

// ---------------------------------------------------------------------------
// Mega GEMM (unchanged): up to 3 tasks, 128x128 tile, BK=32, 256 thr,
// 4-stage cp.async, 3-term hi/lo.
// ---------------------------------------------------------------------------
struct GTask {
    const bf *Ah, *Al, *Bh, *Bl;
    const float *bias, *uvec, *vvec;
    float* Cf;
    bf *Xh, *Xl, *Yh, *Yl;
    int N, K, nbx, mode;
};
struct GT3 { GTask t[3]; int end0, end1; };

#define GSTAGE 37888
__global__ __launch_bounds__(256)
void gemm_mega(GT3 ts)
{
    extern __shared__ char dsm[];
    const int bid = blockIdx.x;
    const int ti = (bid >= ts.end0 ? 1 : 0) + (bid >= ts.end1 ? 1 : 0);
    const GTask T = ts.t[ti];
    const int base = (ti == 0) ? 0 : (ti == 1 ? ts.end0 : ts.end1);
    const int local = bid - base;
    const int by = local / T.nbx, bx = local - by * T.nbx;

    const int tid = threadIdx.x, lane = tid & 31, wid = tid >> 5;
    const int wm = wid >> 1, wn = wid & 1;
    const int m0 = by * 128, n0 = bx * 128;
    const int N = T.N, K = T.K;

    const int lam = tid >> 1;
    const int lac = (tid & 1) * 16;
    const int lbk = tid >> 3;
    const int lbn = (tid & 7) * 16;

    const bf* gAh = T.Ah + (size_t)(m0 + lam) * K + lac;
    const bf* gAl = T.Al + (size_t)(m0 + lam) * K + lac;
    const bf* gBh = T.Bh + (size_t)lbk * N + n0 + lbn;
    const bf* gBl = T.Bl + (size_t)lbk * N + n0 + lbn;

    const uint32_t dA0 = smem_u32(dsm) + lam * 80 + (tid & 1) * 32;
    const uint32_t dB0 = smem_u32(dsm) + 20480 + lbk * 272 + (tid & 7) * 32;

    const int nc = K / 32;

    auto issue = [&](int t) {
        const int s = t & 3;
        const uint32_t da = dA0 + s * GSTAGE;
        const uint32_t db = dB0 + s * GSTAGE;
        const bf* ah = gAh + t * 32;
        const bf* al = gAl + t * 32;
        const bf* bh = gBh + (size_t)t * 32 * N;
        const bf* bl = gBl + (size_t)t * 32 * N;
        CPA(da,          ah);     CPA(da + 16,          ah + 8);
        CPA(da + 10240,  al);     CPA(da + 10240 + 16,  al + 8);
        CPA(db,          bh);     CPA(db + 16,          bh + 8);
        CPA(db + 8704,   bl);     CPA(db + 8704 + 16,   bl + 8);
        CPC();
    };

    issue(0); issue(1); issue(2);

    float acc[2][8][4] = {};

    for (int t = 0; t < nc; t++) {
        cpw_rem(nc - 1 - t);
        __syncthreads();
        if (t + 3 < nc) issue(t + 3);

        char* st = dsm + (t & 3) * GSTAGE;
        bf* sAh = (bf*)st;
        bf* sAl = (bf*)(st + 10240);
        bf* sBh = (bf*)(st + 20480);
        bf* sBl = (bf*)(st + 29184);

        #pragma unroll
        for (int s = 0; s < 2; s++) {
            const int ks = s * 16;
            uint32_t ahf[2][4], alf[2][4], bhf[8][2], blf[8][2];
            #pragma unroll
            for (int f = 0; f < 2; f++) {
                int row = wm * 32 + f * 16 + (lane & 15);
                int kc  = ks + ((lane & 16) >> 1);
                ldsm4(ahf[f], smem_u32(&sAh[row * 40 + kc]));
                ldsm4(alf[f], smem_u32(&sAl[row * 40 + kc]));
            }
            #pragma unroll
            for (int g4 = 0; g4 < 4; g4++) {
                int krow = ks + (lane & 15);
                int ncc  = wn * 64 + g4 * 16 + ((lane & 16) >> 1);
                uint32_t tt[4];
                ldsm4t(tt, smem_u32(&sBh[krow * 136 + ncc]));
                bhf[2*g4][0] = tt[0]; bhf[2*g4][1] = tt[1];
                bhf[2*g4+1][0] = tt[2]; bhf[2*g4+1][1] = tt[3];
                ldsm4t(tt, smem_u32(&sBl[krow * 136 + ncc]));
                blf[2*g4][0] = tt[0]; blf[2*g4][1] = tt[1];
                blf[2*g4+1][0] = tt[2]; blf[2*g4+1][1] = tt[3];
            }
            #pragma unroll
            for (int f = 0; f < 2; f++)
                #pragma unroll
                for (int g = 0; g < 8; g++) {
                    mmabf(acc[f][g], ahf[f], bhf[g]);
                    mmabf(acc[f][g], ahf[f], blf[g]);
                    mmabf(acc[f][g], alf[f], bhf[g]);
                }
        }
    }

    const int r = lane >> 2, c2 = (lane & 3) * 2;
    #pragma unroll
    for (int f = 0; f < 2; f++) {
        int row0 = m0 + wm * 32 + f * 16 + r;
        #pragma unroll
        for (int g = 0; g < 8; g++) {
            int col = n0 + wn * 64 + g * 8 + c2;
            float2 b2 = *(const float2*)&T.bias[col];
            float v00 = acc[f][g][0] + b2.x, v01 = acc[f][g][1] + b2.y;
            float v10 = acc[f][g][2] + b2.x, v11 = acc[f][g][3] + b2.y;
            size_t i0o = (size_t)row0 * N + col;
            size_t i1o = (size_t)(row0 + 8) * N + col;
            if (T.mode == 0) {
                *(float2*)&T.Cf[i0o] = make_float2(v00, v01);
                *(float2*)&T.Cf[i1o] = make_float2(v10, v11);
            } else if (T.mode == 1) {
                store_split(&T.Xh[i0o], &T.Xl[i0o], v00, v01);
                store_split(&T.Xh[i1o], &T.Xl[i1o], v10, v11);
            } else {
                float2 uu = *(const float2*)&T.uvec[col];
                float2 vv = *(const float2*)&T.vvec[col];
                store_split(&T.Xh[i0o], &T.Xl[i0o], 0.125f*(v00 + uu.x), 0.125f*(v01 + uu.y));
                store_split(&T.Xh[i1o], &T.Xl[i1o], 0.125f*(v10 + uu.x), 0.125f*(v11 + uu.y));
                store_split(&T.Yh[i0o], &T.Yl[i0o], 0.125f*(v00 + vv.x), 0.125f*(v01 + vv.y));
                store_split(&T.Yh[i1o], &T.Yl[i1o], 0.125f*(v10 + vv.x), 0.125f*(v11 + vv.y));
            }
        }
    }
}

// ---------------------------------------------------------------------------
// Position scores (unchanged): C2[bh,i,k] = Qv . R (pre-scaled).
// ---------------------------------------------------------------------------
__global__ __launch_bounds__(128)
void pos_scores_bb(const bf* __restrict__ Qvh, const bf* __restrict__ Qvl,
                   const bf* __restrict__ Rh, const bf* __restrict__ Rl,
                   float* __restrict__ C2)
{
    const int bh = blockIdx.z, b = bh >> 4, h = bh & 15;
    const int i0 = blockIdx.y * 64, n0 = blockIdx.x * 64;
    if (n0 + i0 < 385) return;

    __shared__ bf sQh[64][72], sQl[64][72], sRh[64][72], sRl[64][72];

    const int tid = threadIdx.x, lane = tid & 31, wid = tid >> 5;
    const int wm = wid >> 1, wn = wid & 1;

    {
        const int row = tid >> 1, cb = (tid & 1) * 32;
        const size_t qoff = (size_t)((i0 + row) * BS + b) * DIMM + h * HD + cb;
        const size_t roff = (size_t)(n0 + row) * DIMM + h * HD + cb;
        #pragma unroll
        for (int q = 0; q < 4; q++) {
            *(uint4*)&sQh[row][cb + q * 8] = *(const uint4*)&Qvh[qoff + q * 8];
            *(uint4*)&sQl[row][cb + q * 8] = *(const uint4*)&Qvl[qoff + q * 8];
            *(uint4*)&sRh[row][cb + q * 8] = *(const uint4*)&Rh[roff + q * 8];
            *(uint4*)&sRl[row][cb + q * 8] = *(const uint4*)&Rl[roff + q * 8];
        }
    }
    __syncthreads();

    float acc[2][4][4] = {};
    #pragma unroll
    for (int s = 0; s < 4; s++) {
        const int ks = s * 16;
        uint32_t ah[2][4], al[2][4], bh2[4][2], bl2[4][2];
        #pragma unroll
        for (int f = 0; f < 2; f++) {
            int row = wm * 32 + f * 16 + (lane & 15);
            int kc  = ks + ((lane & 16) >> 1);
            ldsm4(ah[f], smem_u32(&sQh[row][kc]));
            ldsm4(al[f], smem_u32(&sQl[row][kc]));
        }
        #pragma unroll
        for (int g4 = 0; g4 < 2; g4++) {
            int nrow = wn * 32 + g4 * 16 + (lane & 15);
            int kc   = ks + ((lane & 16) >> 1);
            uint32_t t[4];
            ldsm4(t, smem_u32(&sRh[nrow][kc]));
            bh2[2*g4][0] = t[0]; bh2[2*g4+1][0] = t[1];
            bh2[2*g4][1] = t[2]; bh2[2*g4+1][1] = t[3];
            ldsm4(t, smem_u32(&sRl[nrow][kc]));
            bl2[2*g4][0] = t[0]; bl2[2*g4+1][0] = t[1];
            bl2[2*g4][1] = t[2]; bl2[2*g4+1][1] = t[3];
        }
        #pragma unroll
        for (int f = 0; f < 2; f++)
            #pragma unroll
            for (int g = 0; g < 4; g++) {
                mmabf(acc[f][g], ah[f], bh2[g]);
                mmabf(acc[f][g], ah[f], bl2[g]);
                mmabf(acc[f][g], al[f], bh2[g]);
            }
    }

    const int r = lane >> 2, c2 = (lane & 3) * 2;
    float* out = C2 + (size_t)bh * CUR * FULL;
    #pragma unroll
    for (int f = 0; f < 2; f++) {
        int row0 = i0 + wm * 32 + f * 16 + r;
        #pragma unroll
        for (int g = 0; g < 4; g++) {
            int col = n0 + wn * 32 + g * 8 + c2;
            *(float2*)&out[(size_t)row0 * FULL + col]       = make_float2(acc[f][g][0], acc[f][g][1]);
            *(float2*)&out[(size_t)(row0 + 8) * FULL + col] = make_float2(acc[f][g][2], acc[f][g][3]);
        }
    }
}

// ---------------------------------------------------------------------------
// Fused attention: 128 rows/block, 256 thr, 2 blocks/SM. Balanced block
// schedule (pairs bid and bid+148 — same SM via classic LUT — to constant
// total work) + per-warp fully-masked-tile skip.
// ---------------------------------------------------------------------------
#define ASTAGE 36864
__global__ __launch_bounds__(256, 2)
void attn_ca(const bf* __restrict__ Quh, const bf* __restrict__ Qul,
             const bf* __restrict__ KVh, const bf* __restrict__ KVl,
             const float* __restrict__ C2,
             bf* __restrict__ AVh, bf* __restrict__ AVl)
{
    extern __shared__ char dsm[];
    __shared__ bf Qh_s[128][72], Ql_s[128][72];

    // Balanced schedule: jtiles(i0_idx) = {10,12,14,16}. Singles (bids
    // 108..147, unpaired on their SM) take heavy blocks; pairs sum to 26.
    const int bid = blockIdx.x;
    int i0_idx, bh;
    if      (bid < 24)  { i0_idx = 3; bh = 40 + bid; }        // heavy, pairs w/ 148..171
    else if (bid < 88)  { i0_idx = 2; bh = bid - 24; }        // 14, pairs w/ 172..235
    else if (bid < 108) { i0_idx = 0; bh = 24 + (bid - 88); } // 10, pairs w/ 236..255
    else if (bid < 148) { i0_idx = 3; bh = bid - 108; }       // heavy singles
    else if (bid < 172) { i0_idx = 0; bh = bid - 148; }       // 10 (+16 = 26)
    else if (bid < 236) { i0_idx = 1; bh = bid - 172; }       // 12 (+14 = 26)
    else                { i0_idx = 0; bh = 44 + (bid - 236); }// 10 (+10 = 20)
    const int i0 = i0_idx * 128;
    const int b = bh >> 4, h = bh & 15;

    const int tid = threadIdx.x, lane = tid & 31, w = tid >> 5;
    const int r = lane >> 2, cq = lane & 3;

    const int jtiles = i0 / 64 + 10;

    const int kii = tid >> 2, kcb = (tid & 3) * 16;
    auto issue_kv = [&](int jt) {
        char* st = dsm + (jt & 1) * ASTAGE;
        const size_t koff = (size_t)((jt * 64 + kii) * BS + b) * (2 * DIMM) + h * HD + kcb;
        const char* gKh = (const char*)(KVh + koff);
        const char* gKl = (const char*)(KVl + koff);
        const char* gVh = (const char*)(KVh + koff + DIMM);
        const char* gVl = (const char*)(KVl + koff + DIMM);
        const uint32_t d = smem_u32(st) + kii * 144 + (tid & 3) * 32;
        #pragma unroll
        for (int c = 0; c < 2; c++) {
            CPA(d +         c * 16, gKh + c * 16);
            CPA(d + 9216  + c * 16, gKl + c * 16);
            CPA(d + 18432 + c * 16, gVh + c * 16);
            CPA(d + 27648 + c * 16, gVl + c * 16);
        }
        CPC();
    };

    issue_kv(0);
    {
        const int qi = tid >> 1, qc = (tid & 1) * 32;
        const size_t qoff = (size_t)((i0 + qi) * BS + b) * DIMM + h * HD + qc;
        #pragma unroll
        for (int q = 0; q < 4; q++) {
            *(uint4*)&Qh_s[qi][qc + q * 8] = *(const uint4*)&Quh[qoff + q * 8];
            *(uint4*)&Ql_s[qi][qc + q * 8] = *(const uint4*)&Qul[qoff + q * 8];
        }
    }
    __syncthreads();

    uint32_t qh[4][4], ql[4][4];
    #pragma unroll
    for (int s = 0; s < 4; s++) {
        int rowi = w * 16 + (lane & 15);
        int kc  = s * 16 + ((lane & 16) >> 1);
        ldsm4(qh[s], smem_u32(&Qh_s[rowi][kc]));
        ldsm4(ql[s], smem_u32(&Ql_s[rowi][kc]));
    }

    float oacc[8][4] = {};
    float m0 = -1e30f, m1 = -1e30f, l0 = 0.f, l1 = 0.f;

    const int irow0 = i0 + w * 16 + r;
    const int jlimit = i0 + w * 16 + 15 + PREV;   // warp's last valid j
    const float* c2row0 = C2 + ((size_t)bh * CUR + irow0) * FULL;
    const float* c2row1 = c2row0 + (size_t)8 * FULL;

    for (int jt = 0; jt < jtiles; jt++) {
        const int j0 = jt * 64;
        CPW(0);
        __syncthreads();
        if (jt + 1 < jtiles) issue_kv(jt + 1);

        if (j0 <= jlimit) {   // warp-uniform: skip fully-masked tiles
        char* st = dsm + (jt & 1) * ASTAGE;
        bf* Kh_s = (bf*)st;
        bf* Kl_s = (bf*)(st + 9216);
        bf* Vh_s = (bf*)(st + 18432);
        bf* Vl_s = (bf*)(st + 27648);

        float sacc[8][4] = {};
        #pragma unroll
        for (int s = 0; s < 4; s++) {
            const int ks = s * 16;
            uint32_t bhf[8][2], blf[8][2];
            #pragma unroll
            for (int g4 = 0; g4 < 4; g4++) {
                int nrow = g4 * 16 + (lane & 15);
                int kc   = ks + ((lane & 16) >> 1);
                uint32_t t[4];
                ldsm4(t, smem_u32(&Kh_s[nrow * 72 + kc]));
                bhf[2*g4][0] = t[0]; bhf[2*g4+1][0] = t[1];
                bhf[2*g4][1] = t[2]; bhf[2*g4+1][1] = t[3];
                ldsm4(t, smem_u32(&Kl_s[nrow * 72 + kc]));
                blf[2*g4][0] = t[0]; blf[2*g4+1][0] = t[1];
                blf[2*g4][1] = t[2]; blf[2*g4+1][1] = t[3];
            }
            #pragma unroll
            for (int g = 0; g < 8; g++) {
                mmabf(sacc[g], qh[s], bhf[g]);
                mmabf(sacc[g], qh[s], blf[g]);
                mmabf(sacc[g], ql[s], bhf[g]);
            }
        }

        const bool need_mask = (j0 + 63 > irow0 + PREV);
        #pragma unroll
        for (int g = 0; g < 8; g++) {
            int jg  = j0 + g * 8 + 2 * cq;
            int k00 = jg - irow0 + 511;
            int k10 = k00 - 8;
            if (!need_mask) {
                sacc[g][0] += c2row0[k00];
                sacc[g][1] += c2row0[k00 + 1];
                sacc[g][2] += c2row1[k10];
                sacc[g][3] += c2row1[k10 + 1];
            } else {
                sacc[g][0] = (k00     <= 1023) ? sacc[g][0] + c2row0[k00]     : -1e30f;
                sacc[g][1] = (k00 + 1 <= 1023) ? sacc[g][1] + c2row0[k00 + 1] : -1e30f;
                sacc[g][2] = (k10     <= 1023) ? sacc[g][2] + c2row1[k10]     : -1e30f;
                sacc[g][3] = (k10 + 1 <= 1023) ? sacc[g][3] + c2row1[k10 + 1] : -1e30f;
            }
        }

        float mx0 = -1e30f, mx1 = -1e30f;
        #pragma unroll
        for (int g = 0; g < 8; g++) {
            mx0 = fmaxf(mx0, fmaxf(sacc[g][0], sacc[g][1]));
            mx1 = fmaxf(mx1, fmaxf(sacc[g][2], sacc[g][3]));
        }
        mx0 = fmaxf(mx0, __shfl_xor_sync(0xffffffffu, mx0, 1));
        mx0 = fmaxf(mx0, __shfl_xor_sync(0xffffffffu, mx0, 2));
        mx1 = fmaxf(mx1, __shfl_xor_sync(0xffffffffu, mx1, 1));
        mx1 = fmaxf(mx1, __shfl_xor_sync(0xffffffffu, mx1, 2));

        float mn0 = fmaxf(m0, mx0), mn1 = fmaxf(m1, mx1);
        float a0 = __expf(m0 - mn0), a1 = __expf(m1 - mn1);
        m0 = mn0; m1 = mn1;
        l0 *= a0; l1 *= a1;
        #pragma unroll
        for (int g = 0; g < 8; g++) {
            oacc[g][0] *= a0; oacc[g][1] *= a0;
            oacc[g][2] *= a1; oacc[g][3] *= a1;
        }

        uint32_t pah[4][4], pal[4][4];
        #pragma unroll
        for (int t4 = 0; t4 < 4; t4++) {
            #pragma unroll
            for (int gg = 0; gg < 2; gg++) {
                int g = 2 * t4 + gg;
                float p0 = __expf(sacc[g][0] - m0);
                float p1 = __expf(sacc[g][1] - m0);
                float p2 = __expf(sacc[g][2] - m1);
                float p3 = __expf(sacc[g][3] - m1);
                l0 += p0 + p1;
                l1 += p2 + p3;
                split2(p0, p1, pah[t4][2*gg],     pal[t4][2*gg]);
                split2(p2, p3, pah[t4][2*gg + 1], pal[t4][2*gg + 1]);
            }
        }

        #pragma unroll
        for (int t4 = 0; t4 < 4; t4++) {
            uint32_t vhf[8][2], vlf[8][2];
            #pragma unroll
            for (int g4 = 0; g4 < 4; g4++) {
                int krow = t4 * 16 + (lane & 15);
                int ncc  = g4 * 16 + ((lane & 16) >> 1);
                uint32_t t[4];
                ldsm4t(t, smem_u32(&Vh_s[krow * 72 + ncc]));
                vhf[2*g4][0] = t[0]; vhf[2*g4][1] = t[1];
                vhf[2*g4+1][0] = t[2]; vhf[2*g4+1][1] = t[3];
                ldsm4t(t, smem_u32(&Vl_s[krow * 72 + ncc]));
                vlf[2*g4][0] = t[0]; vlf[2*g4][1] = t[1];
                vlf[2*g4+1][0] = t[2]; vlf[2*g4+1][1] = t[3];
            }
            #pragma unroll
            for (int g = 0; g < 8; g++) {
                mmabf(oacc[g], pah[t4], vhf[g]);
                mmabf(oacc[g], pah[t4], vlf[g]);
                mmabf(oacc[g], pal[t4], vhf[g]);
            }
        }
        } // j0 <= jlimit
    }

    l0 += __shfl_xor_sync(0xffffffffu, l0, 1);
    l0 += __shfl_xor_sync(0xffffffffu, l0, 2);
    l1 += __shfl_xor_sync(0xffffffffu, l1, 1);
    l1 += __shfl_xor_sync(0xffffffffu, l1, 2);
    const float inv0 = 1.f / l0, inv1 = 1.f / l1;

    const size_t o0 = (size_t)(irow0 * BS + b) * DIMM + h * HD;
    const size_t o1 = (size_t)((irow0 + 8) * BS + b) * DIMM + h * HD;
    #pragma unroll
    for (int g = 0; g < 8; g++) {
        int col = g * 8 + 2 * cq;
        store_split(&AVh[o0 + col], &AVl[o0 + col], oacc[g][0] * inv0, oacc[g][1] * inv0);
        store_split(&AVh[o1 + col], &AVl[o1 + col], oacc[g][2] * inv1, oacc[g][3] * inv1);
    }
}

// ---------------------------------------------------------------------------
// Launch
// ---------------------------------------------------------------------------
extern "C" void kernel_launch(void* const* d_in, const int* in_sizes, int n_in,
                              void* d_out, int out_size)
{
    const float* inputs  = (const float*)d_in[0];
    const float* pos_emb = (const float*)d_in[1];
    const float* full_in = (const float*)d_in[2];
    const float* u       = (const float*)d_in[3];
    const float* v       = (const float*)d_in[4];
    const float* W_kv    = (const float*)d_in[5];
    const float* b_kv    = (const float*)d_in[6];
    const float* W_q     = (const float*)d_in[7];
    const float* b_q     = (const float*)d_in[8];
    const float* W_pos   = (const float*)d_in[9];
    const float* b_pos   = (const float*)d_in[10];
    const float* W_proj  = (const float*)d_in[11];
    const float* b_proj  = (const float*)d_in[12];
    float* out = (float*)d_out;

    bf *FIh, *FIl, *INh, *INl, *PEh, *PEl, *Wkvh, *Wkvl, *Wqh, *Wql,
       *Wph, *Wpl, *Wprh, *Wprl, *KVh, *KVl, *Quh, *Qul, *Qvh, *Qvl,
       *Rh, *Rl, *AVh, *AVl;
    float *C2;
    cudaGetSymbolAddress((void**)&FIh, g_FIh);   cudaGetSymbolAddress((void**)&FIl, g_FIl);
    cudaGetSymbolAddress((void**)&INh, g_INh);   cudaGetSymbolAddress((void**)&INl, g_INl);
    cudaGetSymbolAddress((void**)&PEh, g_PEh);   cudaGetSymbolAddress((void**)&PEl, g_PEl);
    cudaGetSymbolAddress((void**)&Wkvh, g_Wkvh); cudaGetSymbolAddress((void**)&Wkvl, g_Wkvl);
    cudaGetSymbolAddress((void**)&Wqh, g_Wqh);   cudaGetSymbolAddress((void**)&Wql, g_Wql);
    cudaGetSymbolAddress((void**)&Wph, g_Wph);   cudaGetSymbolAddress((void**)&Wpl, g_Wpl);
    cudaGetSymbolAddress((void**)&Wprh, g_Wprh); cudaGetSymbolAddress((void**)&Wprl, g_Wprl);
    cudaGetSymbolAddress((void**)&KVh, g_KVh);   cudaGetSymbolAddress((void**)&KVl, g_KVl);
    cudaGetSymbolAddress((void**)&Quh, g_Quh);   cudaGetSymbolAddress((void**)&Qul, g_Qul);
    cudaGetSymbolAddress((void**)&Qvh, g_Qvh);   cudaGetSymbolAddress((void**)&Qvl, g_Qvl);
    cudaGetSymbolAddress((void**)&Rh, g_Rh);     cudaGetSymbolAddress((void**)&Rl, g_Rl);
    cudaGetSymbolAddress((void**)&AVh, g_AVh);   cudaGetSymbolAddress((void**)&AVl, g_AVl);
    cudaGetSymbolAddress((void**)&C2, g_C2);

    const int GSM = 4 * GSTAGE;     // 151552
    const int ASM = 2 * ASTAGE;     // 73728
    cudaFuncSetAttribute(gemm_mega, cudaFuncAttributeMaxDynamicSharedMemorySize, GSM);
    cudaFuncSetAttribute(attn_ca,   cudaFuncAttributeMaxDynamicSharedMemorySize, ASM);

    // 1. All conversions in one grid
    CT ct;
    ct.s[0] = full_in; ct.h[0] = FIh;  ct.l[0] = FIl;
    ct.s[1] = inputs;  ct.h[1] = INh;  ct.l[1] = INl;
    ct.s[2] = pos_emb; ct.h[2] = PEh;  ct.l[2] = PEl;
    ct.s[3] = W_kv;    ct.h[3] = Wkvh; ct.l[3] = Wkvl;
    ct.s[4] = W_q;     ct.h[4] = Wqh;  ct.l[4] = Wql;
    ct.s[5] = W_pos;   ct.h[5] = Wph;  ct.l[5] = Wpl;
    ct.s[6] = W_proj;  ct.h[6] = Wprh; ct.l[6] = Wprl;
    ct.end[0] = 4096;  ct.end[1] = 6144;  ct.end[2] = 7168;
    ct.end[3] = 9216;  ct.end[4] = 10240; ct.end[5] = 11264; ct.end[6] = 12288;
    cvt_mega<<<12288, 256>>>(ct);

    // 2. Mega GEMM {KV, Q(+u/v, x0.125), R}
    GT3 ts;
    ts.t[0] = { FIh, FIl, Wkvh, Wkvl, b_kv, nullptr, nullptr,
                nullptr, KVh, KVl, nullptr, nullptr, 2048, 1024, 16, 1 };
    ts.t[1] = { INh, INl, Wqh, Wql, b_q, u, v,
                nullptr, Quh, Qul, Qvh, Qvl, 1024, 1024, 8, 2 };
    ts.t[2] = { PEh, PEl, Wph, Wpl, b_pos, nullptr, nullptr,
                nullptr, Rh, Rl, nullptr, nullptr, 1024, 1024, 8, 1 };
    ts.end0 = 512; ts.end1 = 640;
    gemm_mega<<<704, 256, GSM>>>(ts);

    // 3. Position scores (pre-scaled)
    pos_scores_bb<<<dim3(FULL / 64, CUR / 64, BS * NH), 128>>>(Qvh, Qvl, Rh, Rl, C2);

    // 4. Fused attention (balanced 1D schedule)
    attn_ca<<<256, 256, ASM>>>(Quh, Qul, KVh, KVl, C2, AVh, AVl);

    // 5. out = AV @ W_proj + b_proj (fp32)
    GT3 tp;
    tp.t[0] = { AVh, AVl, Wprh, Wprl, b_proj, nullptr, nullptr,
                out, nullptr, nullptr, nullptr, nullptr, 1024, 1024, 8, 0 };
    tp.t[1] = tp.t[0]; tp.t[2] = tp.t[0];
    tp.end0 = 128; tp.end1 = 128;
    gemm_mega<<<128, 256, GSM>>>(tp);
}

// round 14
// speedup vs baseline: 1.0254x; 1.0254x over previous
#include <cuda_runtime.h>
#include <cuda_bf16.h>
#include <cstdint>
#include <cstddef>

#define CUR   512
#define FULL  1024
#define BS    4
#define DIMM  1024
#define NH    16
#define HD    64
#define PREV  512

typedef __nv_bfloat16 bf;

// ---------------- scratch (bf16 hi/lo pairs + fp32 C2 + split-KV partials) --
__device__ __align__(256) bf g_FIh[4194304], g_FIl[4194304];     // full_input
__device__ __align__(256) bf g_INh[2097152], g_INl[2097152];     // inputs
__device__ __align__(256) bf g_PEh[1048576], g_PEl[1048576];     // pos_embedding
__device__ __align__(256) bf g_Wkvh[2097152], g_Wkvl[2097152];
__device__ __align__(256) bf g_Wqh[1048576],  g_Wql[1048576];
__device__ __align__(256) bf g_Wph[1048576],  g_Wpl[1048576];
__device__ __align__(256) bf g_Wprh[1048576], g_Wprl[1048576];
__device__ __align__(256) bf g_KVh[8388608],  g_KVl[8388608];    // (4096,2048) K|V
__device__ __align__(256) bf g_Quh[2097152],  g_Qul[2097152];    // 0.125*(Q+u)
__device__ __align__(256) bf g_Qvh[2097152],  g_Qvl[2097152];    // 0.125*(Q+v)
__device__ __align__(256) bf g_Rh[1048576],   g_Rl[1048576];
__device__ __align__(256) bf g_AVh[2097152],  g_AVl[2097152];
__device__ float g_C2[(size_t)BS * NH * CUR * FULL];
__device__ float g_PO[4194304];   // partial O: [jhalf][bh][row(512)][col(64)]
__device__ float g_Pm[65536];     // partial m: [jhalf][bh][row]
__device__ float g_Pl[65536];     // partial l: [jhalf][bh][row]

// ---------------- helpers ----------------
__device__ __forceinline__ uint32_t smem_u32(const void* p) {
    return (uint32_t)__cvta_generic_to_shared(p);
}
__device__ __forceinline__ void ldsm4(uint32_t* r, uint32_t a) {
    asm volatile("ldmatrix.sync.aligned.m8n8.x4.shared.b16 {%0,%1,%2,%3}, [%4];"
        : "=r"(r[0]), "=r"(r[1]), "=r"(r[2]), "=r"(r[3]) : "r"(a));
}
__device__ __forceinline__ void ldsm4t(uint32_t* r, uint32_t a) {
    asm volatile("ldmatrix.sync.aligned.m8n8.x4.trans.shared.b16 {%0,%1,%2,%3}, [%4];"
        : "=r"(r[0]), "=r"(r[1]), "=r"(r[2]), "=r"(r[3]) : "r"(a));
}
__device__ __forceinline__ void mmabf(float* d, const uint32_t* a, const uint32_t* b) {
    asm volatile(
        "mma.sync.aligned.m16n8k16.row.col.f32.bf16.bf16.f32 "
        "{%0,%1,%2,%3},{%4,%5,%6,%7},{%8,%9},{%0,%1,%2,%3};"
        : "+f"(d[0]), "+f"(d[1]), "+f"(d[2]), "+f"(d[3])
        : "r"(a[0]), "r"(a[1]), "r"(a[2]), "r"(a[3]), "r"(b[0]), "r"(b[1]));
}
__device__ __forceinline__ void store_split(bf* ph, bf* pl, float x, float y) {
    bf hx = __float2bfloat16(x), hy = __float2bfloat16(y);
    __nv_bfloat162 H; H.x = hx; H.y = hy;
    __nv_bfloat162 L;
    L.x = __float2bfloat16(x - __bfloat162float(hx));
    L.y = __float2bfloat16(y - __bfloat162float(hy));
    *(__nv_bfloat162*)ph = H;
    *(__nv_bfloat162*)pl = L;
}
__device__ __forceinline__ void split2(float x, float y, uint32_t& h, uint32_t& l) {
    bf hx = __float2bfloat16(x), hy = __float2bfloat16(y);
    __nv_bfloat162 H; H.x = hx; H.y = hy;
    __nv_bfloat162 L;
    L.x = __float2bfloat16(x - __bfloat162float(hx));
    L.y = __float2bfloat16(y - __bfloat162float(hy));
    h = *reinterpret_cast<uint32_t*>(&H);
    l = *reinterpret_cast<uint32_t*>(&L);
}
#define CPA(dst, src) \
    asm volatile("cp.async.cg.shared.global [%0], [%1], 16;" :: "r"(dst), "l"(src))
#define CPC() asm volatile("cp.async.commit_group;" ::: "memory")
#define CPW(n) asm volatile("cp.async.wait_group %0;" :: "n"(n) : "memory")
__device__ __forceinline__ void cpw_rem(int rem) {
    if (rem >= 2) CPW(2);
    else if (rem == 1) CPW(1);
    else CPW(0);
}

// ---------------- merged converter ----------------
struct CT {
    const float* s[7];
    bf* h[7];
    bf* l[7];
    int end[7];
};
__global__ __launch_bounds__(256)
void cvt_mega(CT c)
{
    const int bid = blockIdx.x;
    int ti = 0;
    #pragma unroll
    for (int k = 0; k < 6; k++) ti += (bid >= c.end[k]) ? 1 : 0;
    const int base = ti ? c.end[ti - 1] : 0;
    const int i = ((bid - base) * 256 + threadIdx.x) * 4;
    const float* x = c.s[ti];
    float4 v = *(const float4*)&x[i];
    store_split(&c.h[ti][i],     &c.l[ti][i],     v.x, v.y);
    store_split(&c.h[ti][i + 2], &c.l[ti][i + 2], v.z, v.w);
}

// ---------------------------------------------------------------------------
// Mega GEMM (unchanged): up to 3 tasks, 128x128 tile, BK=32, 256 thr,
// 4-stage cp.async, 3-term hi/lo.
// ---------------------------------------------------------------------------
struct GTask {
    const bf *Ah, *Al, *Bh, *Bl;
    const float *bias, *uvec, *vvec;
    float* Cf;
    bf *Xh, *Xl, *Yh, *Yl;
    int N, K, nbx, mode;
};
struct GT3 { GTask t[3]; int end0, end1; };

#define GSTAGE 37888
__global__ __launch_bounds__(256)
void gemm_mega(GT3 ts)
{
    extern __shared__ char dsm[];
    const int bid = blockIdx.x;
    const int ti = (bid >= ts.end0 ? 1 : 0) + (bid >= ts.end1 ? 1 : 0);
    const GTask T = ts.t[ti];
    const int base = (ti == 0) ? 0 : (ti == 1 ? ts.end0 : ts.end1);
    const int local = bid - base;
    const int by = local / T.nbx, bx = local - by * T.nbx;

    const int tid = threadIdx.x, lane = tid & 31, wid = tid >> 5;
    const int wm = wid >> 1, wn = wid & 1;
    const int m0 = by * 128, n0 = bx * 128;
    const int N = T.N, K = T.K;

    const int lam = tid >> 1;
    const int lac = (tid & 1) * 16;
    const int lbk = tid >> 3;
    const int lbn = (tid & 7) * 16;

    const bf* gAh = T.Ah + (size_t)(m0 + lam) * K + lac;
    const bf* gAl = T.Al + (size_t)(m0 + lam) * K + lac;
    const bf* gBh = T.Bh + (size_t)lbk * N + n0 + lbn;
    const bf* gBl = T.Bl + (size_t)lbk * N + n0 + lbn;

    const uint32_t dA0 = smem_u32(dsm) + lam * 80 + (tid & 1) * 32;
    const uint32_t dB0 = smem_u32(dsm) + 20480 + lbk * 272 + (tid & 7) * 32;

    const int nc = K / 32;

    auto issue = [&](int t) {
        const int s = t & 3;
        const uint32_t da = dA0 + s * GSTAGE;
        const uint32_t db = dB0 + s * GSTAGE;
        const bf* ah = gAh + t * 32;
        const bf* al = gAl + t * 32;
        const bf* bh = gBh + (size_t)t * 32 * N;
        const bf* bl = gBl + (size_t)t * 32 * N;
        CPA(da,          ah);     CPA(da + 16,          ah + 8);
        CPA(da + 10240,  al);     CPA(da + 10240 + 16,  al + 8);
        CPA(db,          bh);     CPA(db + 16,          bh + 8);
        CPA(db + 8704,   bl);     CPA(db + 8704 + 16,   bl + 8);
        CPC();
    };

    issue(0); issue(1); issue(2);

    float acc[2][8][4] = {};

    for (int t = 0; t < nc; t++) {
        cpw_rem(nc - 1 - t);
        __syncthreads();
        if (t + 3 < nc) issue(t + 3);

        char* st = dsm + (t & 3) * GSTAGE;
        bf* sAh = (bf*)st;
        bf* sAl = (bf*)(st + 10240);
        bf* sBh = (bf*)(st + 20480);
        bf* sBl = (bf*)(st + 29184);

        #pragma unroll
        for (int s = 0; s < 2; s++) {
            const int ks = s * 16;
            uint32_t ahf[2][4], alf[2][4], bhf[8][2], blf[8][2];
            #pragma unroll
            for (int f = 0; f < 2; f++) {
                int row = wm * 32 + f * 16 + (lane & 15);
                int kc  = ks + ((lane & 16) >> 1);
                ldsm4(ahf[f], smem_u32(&sAh[row * 40 + kc]));
                ldsm4(alf[f], smem_u32(&sAl[row * 40 + kc]));
            }
            #pragma unroll
            for (int g4 = 0; g4 < 4; g4++) {
                int krow = ks + (lane & 15);
                int ncc  = wn * 64 + g4 * 16 + ((lane & 16) >> 1);
                uint32_t tt[4];
                ldsm4t(tt, smem_u32(&sBh[krow * 136 + ncc]));
                bhf[2*g4][0] = tt[0]; bhf[2*g4][1] = tt[1];
                bhf[2*g4+1][0] = tt[2]; bhf[2*g4+1][1] = tt[3];
                ldsm4t(tt, smem_u32(&sBl[krow * 136 + ncc]));
                blf[2*g4][0] = tt[0]; blf[2*g4][1] = tt[1];
                blf[2*g4+1][0] = tt[2]; blf[2*g4+1][1] = tt[3];
            }
            #pragma unroll
            for (int f = 0; f < 2; f++)
                #pragma unroll
                for (int g = 0; g < 8; g++) {
                    mmabf(acc[f][g], ahf[f], bhf[g]);
                    mmabf(acc[f][g], ahf[f], blf[g]);
                    mmabf(acc[f][g], alf[f], bhf[g]);
                }
        }
    }

    const int r = lane >> 2, c2 = (lane & 3) * 2;
    #pragma unroll
    for (int f = 0; f < 2; f++) {
        int row0 = m0 + wm * 32 + f * 16 + r;
        #pragma unroll
        for (int g = 0; g < 8; g++) {
            int col = n0 + wn * 64 + g * 8 + c2;
            float2 b2 = *(const float2*)&T.bias[col];
            float v00 = acc[f][g][0] + b2.x, v01 = acc[f][g][1] + b2.y;
            float v10 = acc[f][g][2] + b2.x, v11 = acc[f][g][3] + b2.y;
            size_t i0o = (size_t)row0 * N + col;
            size_t i1o = (size_t)(row0 + 8) * N + col;
            if (T.mode == 0) {
                *(float2*)&T.Cf[i0o] = make_float2(v00, v01);
                *(float2*)&T.Cf[i1o] = make_float2(v10, v11);
            } else if (T.mode == 1) {
                store_split(&T.Xh[i0o], &T.Xl[i0o], v00, v01);
                store_split(&T.Xh[i1o], &T.Xl[i1o], v10, v11);
            } else {
                float2 uu = *(const float2*)&T.uvec[col];
                float2 vv = *(const float2*)&T.vvec[col];
                store_split(&T.Xh[i0o], &T.Xl[i0o], 0.125f*(v00 + uu.x), 0.125f*(v01 + uu.y));
                store_split(&T.Xh[i1o], &T.Xl[i1o], 0.125f*(v10 + uu.x), 0.125f*(v11 + uu.y));
                store_split(&T.Yh[i0o], &T.Yl[i0o], 0.125f*(v00 + vv.x), 0.125f*(v01 + vv.y));
                store_split(&T.Yh[i1o], &T.Yl[i1o], 0.125f*(v10 + vv.x), 0.125f*(v11 + vv.y));
            }
        }
    }
}

// ---------------------------------------------------------------------------
// Position scores (unchanged): C2[bh,i,k] = Qv . R (pre-scaled).
// ---------------------------------------------------------------------------
__global__ __launch_bounds__(128)
void pos_scores_bb(const bf* __restrict__ Qvh, const bf* __restrict__ Qvl,
                   const bf* __restrict__ Rh, const bf* __restrict__ Rl,
                   float* __restrict__ C2)
{
    const int bh = blockIdx.z, b = bh >> 4, h = bh & 15;
    const int i0 = blockIdx.y * 64, n0 = blockIdx.x * 64;
    if (n0 + i0 < 385) return;

    __shared__ bf sQh[64][72], sQl[64][72], sRh[64][72], sRl[64][72];

    const int tid = threadIdx.x, lane = tid & 31, wid = tid >> 5;
    const int wm = wid >> 1, wn = wid & 1;

    {
        const int row = tid >> 1, cb = (tid & 1) * 32;
        const size_t qoff = (size_t)((i0 + row) * BS + b) * DIMM + h * HD + cb;
        const size_t roff = (size_t)(n0 + row) * DIMM + h * HD + cb;
        #pragma unroll
        for (int q = 0; q < 4; q++) {
            *(uint4*)&sQh[row][cb + q * 8] = *(const uint4*)&Qvh[qoff + q * 8];
            *(uint4*)&sQl[row][cb + q * 8] = *(const uint4*)&Qvl[qoff + q * 8];
            *(uint4*)&sRh[row][cb + q * 8] = *(const uint4*)&Rh[roff + q * 8];
            *(uint4*)&sRl[row][cb + q * 8] = *(const uint4*)&Rl[roff + q * 8];
        }
    }
    __syncthreads();

    float acc[2][4][4] = {};
    #pragma unroll
    for (int s = 0; s < 4; s++) {
        const int ks = s * 16;
        uint32_t ah[2][4], al[2][4], bh2[4][2], bl2[4][2];
        #pragma unroll
        for (int f = 0; f < 2; f++) {
            int row = wm * 32 + f * 16 + (lane & 15);
            int kc  = ks + ((lane & 16) >> 1);
            ldsm4(ah[f], smem_u32(&sQh[row][kc]));
            ldsm4(al[f], smem_u32(&sQl[row][kc]));
        }
        #pragma unroll
        for (int g4 = 0; g4 < 2; g4++) {
            int nrow = wn * 32 + g4 * 16 + (lane & 15);
            int kc   = ks + ((lane & 16) >> 1);
            uint32_t t[4];
            ldsm4(t, smem_u32(&sRh[nrow][kc]));
            bh2[2*g4][0] = t[0]; bh2[2*g4+1][0] = t[1];
            bh2[2*g4][1] = t[2]; bh2[2*g4+1][1] = t[3];
            ldsm4(t, smem_u32(&sRl[nrow][kc]));
            bl2[2*g4][0] = t[0]; bl2[2*g4+1][0] = t[1];
            bl2[2*g4][1] = t[2]; bl2[2*g4+1][1] = t[3];
        }
        #pragma unroll
        for (int f = 0; f < 2; f++)
            #pragma unroll
            for (int g = 0; g < 4; g++) {
                mmabf(acc[f][g], ah[f], bh2[g]);
                mmabf(acc[f][g], ah[f], bl2[g]);
                mmabf(acc[f][g], al[f], bh2[g]);
            }
    }

    const int r = lane >> 2, c2 = (lane & 3) * 2;
    float* out = C2 + (size_t)bh * CUR * FULL;
    #pragma unroll
    for (int f = 0; f < 2; f++) {
        int row0 = i0 + wm * 32 + f * 16 + r;
        #pragma unroll
        for (int g = 0; g < 4; g++) {
            int col = n0 + wn * 32 + g * 8 + c2;
            *(float2*)&out[(size_t)row0 * FULL + col]       = make_float2(acc[f][g][0], acc[f][g][1]);
            *(float2*)&out[(size_t)(row0 + 8) * FULL + col] = make_float2(acc[f][g][2], acc[f][g][3]);
        }
    }
}

// ---------------------------------------------------------------------------
// Fused attention, split-KV: grid (8, 64) = (i0blk*2 + jhalf, bh).
// Each block processes half the j-tiles and writes partial (O, m, l) fp32.
// 128 rows/block, 256 thr, 2 blocks/SM.
// ---------------------------------------------------------------------------
#define ASTAGE 36864
__global__ __launch_bounds__(256, 2)
void attn_ca(const bf* __restrict__ Quh, const bf* __restrict__ Qul,
             const bf* __restrict__ KVh, const bf* __restrict__ KVl,
             const float* __restrict__ C2,
             float* __restrict__ PO, float* __restrict__ Pm,
             float* __restrict__ Pl)
{
    extern __shared__ char dsm[];
    __shared__ bf Qh_s[128][72], Ql_s[128][72];

    const int i0blk = blockIdx.x >> 1, jhalf = blockIdx.x & 1;
    const int bh = blockIdx.y, b = bh >> 4, h = bh & 15;
    const int i0 = i0blk * 128;

    const int tid = threadIdx.x, lane = tid & 31, w = tid >> 5;
    const int r = lane >> 2, cq = lane & 3;

    const int jtiles = i0 / 64 + 10;
    const int jhalf0 = jtiles >> 1;
    const int jb = jhalf ? jhalf0 : 0;
    const int je = jhalf ? jtiles : jhalf0;

    const int kii = tid >> 2, kcb = (tid & 3) * 16;
    auto issue_kv = [&](int jt) {
        char* st = dsm + (jt & 1) * ASTAGE;
        const size_t koff = (size_t)((jt * 64 + kii) * BS + b) * (2 * DIMM) + h * HD + kcb;
        const char* gKh = (const char*)(KVh + koff);
        const char* gKl = (const char*)(KVl + koff);
        const char* gVh = (const char*)(KVh + koff + DIMM);
        const char* gVl = (const char*)(KVl + koff + DIMM);
        const uint32_t d = smem_u32(st) + kii * 144 + (tid & 3) * 32;
        #pragma unroll
        for (int c = 0; c < 2; c++) {
            CPA(d +         c * 16, gKh + c * 16);
            CPA(d + 9216  + c * 16, gKl + c * 16);
            CPA(d + 18432 + c * 16, gVh + c * 16);
            CPA(d + 27648 + c * 16, gVl + c * 16);
        }
        CPC();
    };

    issue_kv(jb);
    {
        const int qi = tid >> 1, qc = (tid & 1) * 32;
        const size_t qoff = (size_t)((i0 + qi) * BS + b) * DIMM + h * HD + qc;
        #pragma unroll
        for (int q = 0; q < 4; q++) {
            *(uint4*)&Qh_s[qi][qc + q * 8] = *(const uint4*)&Quh[qoff + q * 8];
            *(uint4*)&Ql_s[qi][qc + q * 8] = *(const uint4*)&Qul[qoff + q * 8];
        }
    }
    __syncthreads();

    uint32_t qh[4][4], ql[4][4];
    #pragma unroll
    for (int s = 0; s < 4; s++) {
        int rowi = w * 16 + (lane & 15);
        int kc  = s * 16 + ((lane & 16) >> 1);
        ldsm4(qh[s], smem_u32(&Qh_s[rowi][kc]));
        ldsm4(ql[s], smem_u32(&Ql_s[rowi][kc]));
    }

    float oacc[8][4] = {};
    float m0 = -1e30f, m1 = -1e30f, l0 = 0.f, l1 = 0.f;

    const int irow0 = i0 + w * 16 + r;
    const int jlimit = i0 + w * 16 + 15 + PREV;   // warp's last valid j
    const float* c2row0 = C2 + ((size_t)bh * CUR + irow0) * FULL;
    const float* c2row1 = c2row0 + (size_t)8 * FULL;

    for (int jt = jb; jt < je; jt++) {
        const int j0 = jt * 64;
        CPW(0);
        __syncthreads();
        if (jt + 1 < je) issue_kv(jt + 1);

        if (j0 <= jlimit) {   // warp-uniform skip of fully-masked tiles
        char* st = dsm + (jt & 1) * ASTAGE;
        bf* Kh_s = (bf*)st;
        bf* Kl_s = (bf*)(st + 9216);
        bf* Vh_s = (bf*)(st + 18432);
        bf* Vl_s = (bf*)(st + 27648);

        float sacc[8][4] = {};
        #pragma unroll
        for (int s = 0; s < 4; s++) {
            const int ks = s * 16;
            uint32_t bhf[8][2], blf[8][2];
            #pragma unroll
            for (int g4 = 0; g4 < 4; g4++) {
                int nrow = g4 * 16 + (lane & 15);
                int kc   = ks + ((lane & 16) >> 1);
                uint32_t t[4];
                ldsm4(t, smem_u32(&Kh_s[nrow * 72 + kc]));
                bhf[2*g4][0] = t[0]; bhf[2*g4+1][0] = t[1];
                bhf[2*g4][1] = t[2]; bhf[2*g4+1][1] = t[3];
                ldsm4(t, smem_u32(&Kl_s[nrow * 72 + kc]));
                blf[2*g4][0] = t[0]; blf[2*g4+1][0] = t[1];
                blf[2*g4][1] = t[2]; blf[2*g4+1][1] = t[3];
            }
            #pragma unroll
            for (int g = 0; g < 8; g++) {
                mmabf(sacc[g], qh[s], bhf[g]);
                mmabf(sacc[g], qh[s], blf[g]);
                mmabf(sacc[g], ql[s], bhf[g]);
            }
        }

        const bool need_mask = (j0 + 63 > irow0 + PREV);
        #pragma unroll
        for (int g = 0; g < 8; g++) {
            int jg  = j0 + g * 8 + 2 * cq;
            int k00 = jg - irow0 + 511;
            int k10 = k00 - 8;
            if (!need_mask) {
                sacc[g][0] += c2row0[k00];
                sacc[g][1] += c2row0[k00 + 1];
                sacc[g][2] += c2row1[k10];
                sacc[g][3] += c2row1[k10 + 1];
            } else {
                sacc[g][0] = (k00     <= 1023) ? sacc[g][0] + c2row0[k00]     : -1e30f;
                sacc[g][1] = (k00 + 1 <= 1023) ? sacc[g][1] + c2row0[k00 + 1] : -1e30f;
                sacc[g][2] = (k10     <= 1023) ? sacc[g][2] + c2row1[k10]     : -1e30f;
                sacc[g][3] = (k10 + 1 <= 1023) ? sacc[g][3] + c2row1[k10 + 1] : -1e30f;
            }
        }

        float mx0 = -1e30f, mx1 = -1e30f;
        #pragma unroll
        for (int g = 0; g < 8; g++) {
            mx0 = fmaxf(mx0, fmaxf(sacc[g][0], sacc[g][1]));
            mx1 = fmaxf(mx1, fmaxf(sacc[g][2], sacc[g][3]));
        }
        mx0 = fmaxf(mx0, __shfl_xor_sync(0xffffffffu, mx0, 1));
        mx0 = fmaxf(mx0, __shfl_xor_sync(0xffffffffu, mx0, 2));
        mx1 = fmaxf(mx1, __shfl_xor_sync(0xffffffffu, mx1, 1));
        mx1 = fmaxf(mx1, __shfl_xor_sync(0xffffffffu, mx1, 2));

        float mn0 = fmaxf(m0, mx0), mn1 = fmaxf(m1, mx1);
        float a0 = __expf(m0 - mn0), a1 = __expf(m1 - mn1);
        m0 = mn0; m1 = mn1;
        l0 *= a0; l1 *= a1;
        #pragma unroll
        for (int g = 0; g < 8; g++) {
            oacc[g][0] *= a0; oacc[g][1] *= a0;
            oacc[g][2] *= a1; oacc[g][3] *= a1;
        }

        uint32_t pah[4][4], pal[4][4];
        #pragma unroll
        for (int t4 = 0; t4 < 4; t4++) {
            #pragma unroll
            for (int gg = 0; gg < 2; gg++) {
                int g = 2 * t4 + gg;
                float p0 = __expf(sacc[g][0] - m0);
                float p1 = __expf(sacc[g][1] - m0);
                float p2 = __expf(sacc[g][2] - m1);
                float p3 = __expf(sacc[g][3] - m1);
                l0 += p0 + p1;
                l1 += p2 + p3;
                split2(p0, p1, pah[t4][2*gg],     pal[t4][2*gg]);
                split2(p2, p3, pah[t4][2*gg + 1], pal[t4][2*gg + 1]);
            }
        }

        #pragma unroll
        for (int t4 = 0; t4 < 4; t4++) {
            uint32_t vhf[8][2], vlf[8][2];
            #pragma unroll
            for (int g4 = 0; g4 < 4; g4++) {
                int krow = t4 * 16 + (lane & 15);
                int ncc  = g4 * 16 + ((lane & 16) >> 1);
                uint32_t t[4];
                ldsm4t(t, smem_u32(&Vh_s[krow * 72 + ncc]));
                vhf[2*g4][0] = t[0]; vhf[2*g4][1] = t[1];
                vhf[2*g4+1][0] = t[2]; vhf[2*g4+1][1] = t[3];
                ldsm4t(t, smem_u32(&Vl_s[krow * 72 + ncc]));
                vlf[2*g4][0] = t[0]; vlf[2*g4][1] = t[1];
                vlf[2*g4+1][0] = t[2]; vlf[2*g4+1][1] = t[3];
            }
            #pragma unroll
            for (int g = 0; g < 8; g++) {
                mmabf(oacc[g], pah[t4], vhf[g]);
                mmabf(oacc[g], pah[t4], vlf[g]);
                mmabf(oacc[g], pal[t4], vhf[g]);
            }
        }
        } // j0 <= jlimit
    }

    // Reduce l across quad, write partials (unnormalized O, m, l).
    l0 += __shfl_xor_sync(0xffffffffu, l0, 1);
    l0 += __shfl_xor_sync(0xffffffffu, l0, 2);
    l1 += __shfl_xor_sync(0xffffffffu, l1, 1);
    l1 += __shfl_xor_sync(0xffffffffu, l1, 2);

    const size_t pbase = ((size_t)(jhalf * 64 + bh)) * CUR;
    if (cq == 0) {
        Pm[pbase + irow0]     = m0;  Pl[pbase + irow0]     = l0;
        Pm[pbase + irow0 + 8] = m1;  Pl[pbase + irow0 + 8] = l1;
    }
    float* po0 = PO + (pbase + irow0) * 64;
    float* po1 = PO + (pbase + irow0 + 8) * 64;
    #pragma unroll
    for (int g = 0; g < 8; g++) {
        int col = g * 8 + 2 * cq;
        *(float2*)&po0[col] = make_float2(oacc[g][0], oacc[g][1]);
        *(float2*)&po1[col] = make_float2(oacc[g][2], oacc[g][3]);
    }
}

// ---------------------------------------------------------------------------
// Split-KV combine: AV[row, bh, col] = (O0*f0 + O1*f1) / (l0*f0 + l1*f1),
// f = exp(m - max(m0, m1)). Emits split bf16.
// ---------------------------------------------------------------------------
__global__ __launch_bounds__(256)
void attn_combine(const float* __restrict__ PO, const float* __restrict__ Pm,
                  const float* __restrict__ Pl,
                  bf* __restrict__ AVh, bf* __restrict__ AVl)
{
    // one thread = one (bh, row, 8-col chunk); total 64*512*8 threads
    const int t = blockIdx.x * 256 + threadIdx.x;
    const int bh = t >> 12;
    const int rem = t & 4095;
    const int row = rem >> 3;
    const int colg = (rem & 7) * 8;
    const int b = bh >> 4, h = bh & 15;

    const size_t r0 = (size_t)bh * CUR + row;
    const size_t r1 = (size_t)(64 + bh) * CUR + row;
    const float m0 = Pm[r0], m1 = Pm[r1];
    const float l0 = Pl[r0], l1 = Pl[r1];
    const float ms = fmaxf(m0, m1);
    const float f0 = __expf(m0 - ms), f1 = __expf(m1 - ms);
    const float inv = 1.f / (l0 * f0 + l1 * f1);

    const float* po0 = PO + r0 * 64 + colg;
    const float* po1 = PO + r1 * 64 + colg;
    bf* oh = AVh + (size_t)(row * BS + b) * DIMM + h * HD + colg;
    bf* ol = AVl + (size_t)(row * BS + b) * DIMM + h * HD + colg;

    #pragma unroll
    for (int c = 0; c < 8; c += 2) {
        float2 a = *(const float2*)&po0[c];
        float2 d = *(const float2*)&po1[c];
        float x = (a.x * f0 + d.x * f1) * inv;
        float y = (a.y * f0 + d.y * f1) * inv;
        store_split(&oh[c], &ol[c], x, y);
    }
}

// ---------------------------------------------------------------------------
// Launch
// ---------------------------------------------------------------------------
extern "C" void kernel_launch(void* const* d_in, const int* in_sizes, int n_in,
                              void* d_out, int out_size)
{
    const float* inputs  = (const float*)d_in[0];
    const float* pos_emb = (const float*)d_in[1];
    const float* full_in = (const float*)d_in[2];
    const float* u       = (const float*)d_in[3];
    const float* v       = (const float*)d_in[4];
    const float* W_kv    = (const float*)d_in[5];
    const float* b_kv    = (const float*)d_in[6];
    const float* W_q     = (const float*)d_in[7];
    const float* b_q     = (const float*)d_in[8];
    const float* W_pos   = (const float*)d_in[9];
    const float* b_pos   = (const float*)d_in[10];
    const float* W_proj  = (const float*)d_in[11];
    const float* b_proj  = (const float*)d_in[12];
    float* out = (float*)d_out;

    bf *FIh, *FIl, *INh, *INl, *PEh, *PEl, *Wkvh, *Wkvl, *Wqh, *Wql,
       *Wph, *Wpl, *Wprh, *Wprl, *KVh, *KVl, *Quh, *Qul, *Qvh, *Qvl,
       *Rh, *Rl, *AVh, *AVl;
    float *C2, *PO, *Pm, *Pl;
    cudaGetSymbolAddress((void**)&FIh, g_FIh);   cudaGetSymbolAddress((void**)&FIl, g_FIl);
    cudaGetSymbolAddress((void**)&INh, g_INh);   cudaGetSymbolAddress((void**)&INl, g_INl);
    cudaGetSymbolAddress((void**)&PEh, g_PEh);   cudaGetSymbolAddress((void**)&PEl, g_PEl);
    cudaGetSymbolAddress((void**)&Wkvh, g_Wkvh); cudaGetSymbolAddress((void**)&Wkvl, g_Wkvl);
    cudaGetSymbolAddress((void**)&Wqh, g_Wqh);   cudaGetSymbolAddress((void**)&Wql, g_Wql);
    cudaGetSymbolAddress((void**)&Wph, g_Wph);   cudaGetSymbolAddress((void**)&Wpl, g_Wpl);
    cudaGetSymbolAddress((void**)&Wprh, g_Wprh); cudaGetSymbolAddress((void**)&Wprl, g_Wprl);
    cudaGetSymbolAddress((void**)&KVh, g_KVh);   cudaGetSymbolAddress((void**)&KVl, g_KVl);
    cudaGetSymbolAddress((void**)&Quh, g_Quh);   cudaGetSymbolAddress((void**)&Qul, g_Qul);
    cudaGetSymbolAddress((void**)&Qvh, g_Qvh);   cudaGetSymbolAddress((void**)&Qvl, g_Qvl);
    cudaGetSymbolAddress((void**)&Rh, g_Rh);     cudaGetSymbolAddress((void**)&Rl, g_Rl);
    cudaGetSymbolAddress((void**)&AVh, g_AVh);   cudaGetSymbolAddress((void**)&AVl, g_AVl);
    cudaGetSymbolAddress((void**)&C2, g_C2);
    cudaGetSymbolAddress((void**)&PO, g_PO);
    cudaGetSymbolAddress((void**)&Pm, g_Pm);
    cudaGetSymbolAddress((void**)&Pl, g_Pl);

    const int GSM = 4 * GSTAGE;     // 151552
    const int ASM = 2 * ASTAGE;     // 73728
    cudaFuncSetAttribute(gemm_mega, cudaFuncAttributeMaxDynamicSharedMemorySize, GSM);
    cudaFuncSetAttribute(attn_ca,   cudaFuncAttributeMaxDynamicSharedMemorySize, ASM);

    // 1. All conversions in one grid
    CT ct;
    ct.s[0] = full_in; ct.h[0] = FIh;  ct.l[0] = FIl;
    ct.s[1] = inputs;  ct.h[1] = INh;  ct.l[1] = INl;
    ct.s[2] = pos_emb; ct.h[2] = PEh;  ct.l[2] = PEl;
    ct.s[3] = W_kv;    ct.h[3] = Wkvh; ct.l[3] = Wkvl;
    ct.s[4] = W_q;     ct.h[4] = Wqh;  ct.l[4] = Wql;
    ct.s[5] = W_pos;   ct.h[5] = Wph;  ct.l[5] = Wpl;
    ct.s[6] = W_proj;  ct.h[6] = Wprh; ct.l[6] = Wprl;
    ct.end[0] = 4096;  ct.end[1] = 6144;  ct.end[2] = 7168;
    ct.end[3] = 9216;  ct.end[4] = 10240; ct.end[5] = 11264; ct.end[6] = 12288;
    cvt_mega<<<12288, 256>>>(ct);

    // 2. Mega GEMM {KV, Q(+u/v, x0.125), R}
    GT3 ts;
    ts.t[0] = { FIh, FIl, Wkvh, Wkvl, b_kv, nullptr, nullptr,
                nullptr, KVh, KVl, nullptr, nullptr, 2048, 1024, 16, 1 };
    ts.t[1] = { INh, INl, Wqh, Wql, b_q, u, v,
                nullptr, Quh, Qul, Qvh, Qvl, 1024, 1024, 8, 2 };
    ts.t[2] = { PEh, PEl, Wph, Wpl, b_pos, nullptr, nullptr,
                nullptr, Rh, Rl, nullptr, nullptr, 1024, 1024, 8, 1 };
    ts.end0 = 512; ts.end1 = 640;
    gemm_mega<<<704, 256, GSM>>>(ts);

    // 3. Position scores (pre-scaled)
    pos_scores_bb<<<dim3(FULL / 64, CUR / 64, BS * NH), 128>>>(Qvh, Qvl, Rh, Rl, C2);

    // 4a. Fused attention, split-KV (partials)
    attn_ca<<<dim3(8, BS * NH), 256, ASM>>>(Quh, Qul, KVh, KVl, C2, PO, Pm, Pl);

    // 4b. Combine partials -> AV (split bf16)
    attn_combine<<<(64 * 512 * 8) / 256, 256>>>(PO, Pm, Pl, AVh, AVl);

    // 5. out = AV @ W_proj + b_proj (fp32)
    GT3 tp;
    tp.t[0] = { AVh, AVl, Wprh, Wprl, b_proj, nullptr, nullptr,
                out, nullptr, nullptr, nullptr, nullptr, 1024, 1024, 8, 0 };
    tp.t[1] = tp.t[0]; tp.t[2] = tp.t[0];
    tp.end0 = 128; tp.end1 = 128;
    gemm_mega<<<128, 256, GSM>>>(tp);
}

// round 15
// speedup vs baseline: 1.3715x; 1.3375x over previous
#include <cuda_runtime.h>
#include <cuda_fp16.h>
#include <cstdint>
#include <cstddef>

#define CUR   512
#define FULL  1024
#define BS    4
#define DIMM  1024
#define NH    16
#define HD    64
#define PREV  512

typedef __half hf;

// ---------------- scratch ----------------
// activations: exact fp16 hi/lo pairs; weights/K/V/R: single fp16
__device__ __align__(256) hf g_FIh[4194304], g_FIl[4194304];
__device__ __align__(256) hf g_INh[2097152], g_INl[2097152];
__device__ __align__(256) hf g_PEh[1048576], g_PEl[1048576];
__device__ __align__(256) hf g_Wkv[2097152];
__device__ __align__(256) hf g_Wq[1048576];
__device__ __align__(256) hf g_Wp[1048576];
__device__ __align__(256) hf g_Wpr[1048576];
__device__ __align__(256) hf g_KV[8388608];                    // (4096,2048) K|V single
__device__ __align__(256) hf g_Quh[2097152], g_Qul[2097152];   // 0.125*(Q+u) split
__device__ __align__(256) hf g_Qvh[2097152], g_Qvl[2097152];   // 0.125*(Q+v) split
__device__ __align__(256) hf g_R[1048576];                     // single
__device__ __align__(256) hf g_AVh[2097152], g_AVl[2097152];   // split
__device__ float g_C2[(size_t)BS * NH * CUR * FULL];
__device__ float g_PO[4194304];
__device__ float g_Pm[65536];
__device__ float g_Pl[65536];

// ---------------- helpers ----------------
__device__ __forceinline__ uint32_t smem_u32(const void* p) {
    return (uint32_t)__cvta_generic_to_shared(p);
}
__device__ __forceinline__ void ldsm4(uint32_t* r, uint32_t a) {
    asm volatile("ldmatrix.sync.aligned.m8n8.x4.shared.b16 {%0,%1,%2,%3}, [%4];"
        : "=r"(r[0]), "=r"(r[1]), "=r"(r[2]), "=r"(r[3]) : "r"(a));
}
__device__ __forceinline__ void ldsm4t(uint32_t* r, uint32_t a) {
    asm volatile("ldmatrix.sync.aligned.m8n8.x4.trans.shared.b16 {%0,%1,%2,%3}, [%4];"
        : "=r"(r[0]), "=r"(r[1]), "=r"(r[2]), "=r"(r[3]) : "r"(a));
}
__device__ __forceinline__ void mmah(float* d, const uint32_t* a, const uint32_t* b) {
    asm volatile(
        "mma.sync.aligned.m16n8k16.row.col.f32.f16.f16.f32 "
        "{%0,%1,%2,%3},{%4,%5,%6,%7},{%8,%9},{%0,%1,%2,%3};"
        : "+f"(d[0]), "+f"(d[1]), "+f"(d[2]), "+f"(d[3])
        : "r"(a[0]), "r"(a[1]), "r"(a[2]), "r"(a[3]), "r"(b[0]), "r"(b[1]));
}
__device__ __forceinline__ void sth2(hf* p, float x, float y) {
    __half2 t; t.x = __float2half_rn(x); t.y = __float2half_rn(y);
    *(__half2*)p = t;
}
__device__ __forceinline__ void store_split_h(hf* ph, hf* pl, float x, float y) {
    hf hx = __float2half_rn(x), hy = __float2half_rn(y);
    __half2 H; H.x = hx; H.y = hy;
    __half2 L;
    L.x = __float2half_rn(x - __half2float(hx));
    L.y = __float2half_rn(y - __half2float(hy));
    *(__half2*)ph = H;
    *(__half2*)pl = L;
}
__device__ __forceinline__ void split2h(float x, float y, uint32_t& h, uint32_t& l) {
    hf hx = __float2half_rn(x), hy = __float2half_rn(y);
    __half2 H; H.x = hx; H.y = hy;
    __half2 L;
    L.x = __float2half_rn(x - __half2float(hx));
    L.y = __float2half_rn(y - __half2float(hy));
    h = *reinterpret_cast<uint32_t*>(&H);
    l = *reinterpret_cast<uint32_t*>(&L);
}
#define CPA(dst, src) \
    asm volatile("cp.async.cg.shared.global [%0], [%1], 16;" :: "r"(dst), "l"(src))
#define CPC() asm volatile("cp.async.commit_group;" ::: "memory")
#define CPW(n) asm volatile("cp.async.wait_group %0;" :: "n"(n) : "memory")
__device__ __forceinline__ void cpw_rem(int rem) {
    if (rem >= 2) CPW(2);
    else if (rem == 1) CPW(1);
    else CPW(0);
}

// ---------------- merged converter (split or single per task) ----------------
struct CT {
    const float* s[7];
    hf* h[7];
    hf* l[7];
    int end[7];
    int md[7];           // 1 = split pair, 0 = single
};
__global__ __launch_bounds__(256)
void cvt_mega(CT c)
{
    const int bid = blockIdx.x;
    int ti = 0;
    #pragma unroll
    for (int k = 0; k < 6; k++) ti += (bid >= c.end[k]) ? 1 : 0;
    const int base = ti ? c.end[ti - 1] : 0;
    const int i = ((bid - base) * 256 + threadIdx.x) * 4;
    float4 v = *(const float4*)&c.s[ti][i];
    if (c.md[ti]) {
        store_split_h(&c.h[ti][i],     &c.l[ti][i],     v.x, v.y);
        store_split_h(&c.h[ti][i + 2], &c.l[ti][i + 2], v.z, v.w);
    } else {
        sth2(&c.h[ti][i],     v.x, v.y);
        sth2(&c.h[ti][i + 2], v.z, v.w);
    }
}

// ---------------------------------------------------------------------------
// Mega GEMM: C = A(split fp16) * B(single fp16) (+bias). 128x128, BK=32,
// 256 thr, 8 warps (4m x 2n), warp tile 32x64, 2-mma/product, 4-stage cp.async.
// Stage (29184B): Ah[128][40] | Al[128][40] | B[32][136].
// mode 0: fp32 out. mode 1: single fp16 out. mode 2: dual split 0.125*(+u/v).
// ---------------------------------------------------------------------------
struct GTask {
    const hf *Ah, *Al, *B;
    const float *bias, *uvec, *vvec;
    float* Cf;
    hf *Xh, *Xl, *Yh, *Yl;
    int N, K, nbx, mode;
};
struct GT3 { GTask t[3]; int end0, end1; };

#define GSTAGE 29184
__global__ __launch_bounds__(256)
void gemm_mega(GT3 ts)
{
    extern __shared__ char dsm[];
    const int bid = blockIdx.x;
    const int ti = (bid >= ts.end0 ? 1 : 0) + (bid >= ts.end1 ? 1 : 0);
    const GTask T = ts.t[ti];
    const int base = (ti == 0) ? 0 : (ti == 1 ? ts.end0 : ts.end1);
    const int local = bid - base;
    const int by = local / T.nbx, bx = local - by * T.nbx;

    const int tid = threadIdx.x, lane = tid & 31, wid = tid >> 5;
    const int wm = wid >> 1, wn = wid & 1;
    const int m0 = by * 128, n0 = bx * 128;
    const int N = T.N, K = T.K;

    const int lam = tid >> 1, lac = (tid & 1) * 16;
    const int lbk = tid >> 3, lbn = (tid & 7) * 16;

    const hf* gAh = T.Ah + (size_t)(m0 + lam) * K + lac;
    const hf* gAl = T.Al + (size_t)(m0 + lam) * K + lac;
    const hf* gB  = T.B  + (size_t)lbk * N + n0 + lbn;

    const uint32_t dA0 = smem_u32(dsm) + lam * 80 + (tid & 1) * 32;
    const uint32_t dB0 = smem_u32(dsm) + 20480 + lbk * 272 + (tid & 7) * 32;

    const int nc = K / 32;

    auto issue = [&](int t) {
        const int s = t & 3;
        const uint32_t da = dA0 + s * GSTAGE;
        const uint32_t db = dB0 + s * GSTAGE;
        const hf* ah = gAh + t * 32;
        const hf* al = gAl + t * 32;
        const hf* bb = gB + (size_t)t * 32 * N;
        CPA(da,         ah);  CPA(da + 16,         ah + 8);
        CPA(da + 10240, al);  CPA(da + 10240 + 16, al + 8);
        CPA(db,         bb);  CPA(db + 16,         bb + 8);
        CPC();
    };

    issue(0); issue(1); issue(2);

    float acc[2][8][4] = {};

    for (int t = 0; t < nc; t++) {
        cpw_rem(nc - 1 - t);
        __syncthreads();
        if (t + 3 < nc) issue(t + 3);

        char* st = dsm + (t & 3) * GSTAGE;
        hf* sAh = (hf*)st;
        hf* sAl = (hf*)(st + 10240);
        hf* sB  = (hf*)(st + 20480);

        #pragma unroll
        for (int s = 0; s < 2; s++) {
            const int ks = s * 16;
            uint32_t ahf[2][4], alf[2][4], bhf[8][2];
            #pragma unroll
            for (int f = 0; f < 2; f++) {
                int row = wm * 32 + f * 16 + (lane & 15);
                int kc  = ks + ((lane & 16) >> 1);
                ldsm4(ahf[f], smem_u32(&sAh[row * 40 + kc]));
                ldsm4(alf[f], smem_u32(&sAl[row * 40 + kc]));
            }
            #pragma unroll
            for (int g4 = 0; g4 < 4; g4++) {
                int krow = ks + (lane & 15);
                int ncc  = wn * 64 + g4 * 16 + ((lane & 16) >> 1);
                uint32_t tt[4];
                ldsm4t(tt, smem_u32(&sB[krow * 136 + ncc]));
                bhf[2*g4][0] = tt[0]; bhf[2*g4][1] = tt[1];
                bhf[2*g4+1][0] = tt[2]; bhf[2*g4+1][1] = tt[3];
            }
            #pragma unroll
            for (int f = 0; f < 2; f++)
                #pragma unroll
                for (int g = 0; g < 8; g++) {
                    mmah(acc[f][g], ahf[f], bhf[g]);
                    mmah(acc[f][g], alf[f], bhf[g]);
                }
        }
    }

    const int r = lane >> 2, c2 = (lane & 3) * 2;
    #pragma unroll
    for (int f = 0; f < 2; f++) {
        int row0 = m0 + wm * 32 + f * 16 + r;
        #pragma unroll
        for (int g = 0; g < 8; g++) {
            int col = n0 + wn * 64 + g * 8 + c2;
            float2 b2 = *(const float2*)&T.bias[col];
            float v00 = acc[f][g][0] + b2.x, v01 = acc[f][g][1] + b2.y;
            float v10 = acc[f][g][2] + b2.x, v11 = acc[f][g][3] + b2.y;
            size_t i0o = (size_t)row0 * N + col;
            size_t i1o = (size_t)(row0 + 8) * N + col;
            if (T.mode == 0) {
                *(float2*)&T.Cf[i0o] = make_float2(v00, v01);
                *(float2*)&T.Cf[i1o] = make_float2(v10, v11);
            } else if (T.mode == 1) {
                sth2(&T.Xh[i0o], v00, v01);
                sth2(&T.Xh[i1o], v10, v11);
            } else {
                float2 uu = *(const float2*)&T.uvec[col];
                float2 vv = *(const float2*)&T.vvec[col];
                store_split_h(&T.Xh[i0o], &T.Xl[i0o], 0.125f*(v00 + uu.x), 0.125f*(v01 + uu.y));
                store_split_h(&T.Xh[i1o], &T.Xl[i1o], 0.125f*(v10 + uu.x), 0.125f*(v11 + uu.y));
                store_split_h(&T.Yh[i0o], &T.Yl[i0o], 0.125f*(v00 + vv.x), 0.125f*(v01 + vv.y));
                store_split_h(&T.Yh[i1o], &T.Yl[i1o], 0.125f*(v10 + vv.x), 0.125f*(v11 + vv.y));
            }
        }
    }
}

// ---------------------------------------------------------------------------
// Position scores: C2 = Qv(split) . R(single), 2-mma. 64x64 tile, 128 thr.
// ---------------------------------------------------------------------------
__global__ __launch_bounds__(128)
void pos_scores_bb(const hf* __restrict__ Qvh, const hf* __restrict__ Qvl,
                   const hf* __restrict__ R, float* __restrict__ C2)
{
    const int bh = blockIdx.z, b = bh >> 4, h = bh & 15;
    const int i0 = blockIdx.y * 64, n0 = blockIdx.x * 64;
    if (n0 + i0 < 385) return;

    __shared__ hf sQh[64][72], sQl[64][72], sR[64][72];

    const int tid = threadIdx.x, lane = tid & 31, wid = tid >> 5;
    const int wm = wid >> 1, wn = wid & 1;

    {
        const int row = tid >> 1, cb = (tid & 1) * 32;
        const size_t qoff = (size_t)((i0 + row) * BS + b) * DIMM + h * HD + cb;
        const size_t roff = (size_t)(n0 + row) * DIMM + h * HD + cb;
        #pragma unroll
        for (int q = 0; q < 4; q++) {
            *(uint4*)&sQh[row][cb + q * 8] = *(const uint4*)&Qvh[qoff + q * 8];
            *(uint4*)&sQl[row][cb + q * 8] = *(const uint4*)&Qvl[qoff + q * 8];
            *(uint4*)&sR[row][cb + q * 8]  = *(const uint4*)&R[roff + q * 8];
        }
    }
    __syncthreads();

    float acc[2][4][4] = {};
    #pragma unroll
    for (int s = 0; s < 4; s++) {
        const int ks = s * 16;
        uint32_t ah[2][4], al[2][4], bh2[4][2];
        #pragma unroll
        for (int f = 0; f < 2; f++) {
            int row = wm * 32 + f * 16 + (lane & 15);
            int kc  = ks + ((lane & 16) >> 1);
            ldsm4(ah[f], smem_u32(&sQh[row][kc]));
            ldsm4(al[f], smem_u32(&sQl[row][kc]));
        }
        #pragma unroll
        for (int g4 = 0; g4 < 2; g4++) {
            int nrow = wn * 32 + g4 * 16 + (lane & 15);
            int kc   = ks + ((lane & 16) >> 1);
            uint32_t t[4];
            ldsm4(t, smem_u32(&sR[nrow][kc]));
            bh2[2*g4][0] = t[0]; bh2[2*g4+1][0] = t[1];
            bh2[2*g4][1] = t[2]; bh2[2*g4+1][1] = t[3];
        }
        #pragma unroll
        for (int f = 0; f < 2; f++)
            #pragma unroll
            for (int g = 0; g < 4; g++) {
                mmah(acc[f][g], ah[f], bh2[g]);
                mmah(acc[f][g], al[f], bh2[g]);
            }
    }

    const int r = lane >> 2, c2 = (lane & 3) * 2;
    float* out = C2 + (size_t)bh * CUR * FULL;
    #pragma unroll
    for (int f = 0; f < 2; f++) {
        int row0 = i0 + wm * 32 + f * 16 + r;
        #pragma unroll
        for (int g = 0; g < 4; g++) {
            int col = n0 + wn * 32 + g * 8 + c2;
            *(float2*)&out[(size_t)row0 * FULL + col]       = make_float2(acc[f][g][0], acc[f][g][1]);
            *(float2*)&out[(size_t)(row0 + 8) * FULL + col] = make_float2(acc[f][g][2], acc[f][g][3]);
        }
    }
}

// ---------------------------------------------------------------------------
// Fused attention, split-KV. Q split fp16, K/V single fp16 (half the traffic).
// grid (8, 64) = (i0blk*2 + jhalf, bh). Partials (O, m, l) fp32.
// ---------------------------------------------------------------------------
#define ASTAGE 18432
__global__ __launch_bounds__(256, 2)
void attn_ca(const hf* __restrict__ Quh, const hf* __restrict__ Qul,
             const hf* __restrict__ KV, const float* __restrict__ C2,
             float* __restrict__ PO, float* __restrict__ Pm,
             float* __restrict__ Pl)
{
    extern __shared__ char dsm[];
    __shared__ hf Qh_s[128][72], Ql_s[128][72];

    const int i0blk = blockIdx.x >> 1, jhalf = blockIdx.x & 1;
    const int bh = blockIdx.y, b = bh >> 4, h = bh & 15;
    const int i0 = i0blk * 128;

    const int tid = threadIdx.x, lane = tid & 31, w = tid >> 5;
    const int r = lane >> 2, cq = lane & 3;

    const int jtiles = i0 / 64 + 10;
    const int jhalf0 = jtiles >> 1;
    const int jb = jhalf ? jhalf0 : 0;
    const int je = jhalf ? jtiles : jhalf0;

    const int kii = tid >> 2, kcb = (tid & 3) * 16;
    auto issue_kv = [&](int jt) {
        char* st = dsm + (jt & 1) * ASTAGE;
        const size_t koff = (size_t)((jt * 64 + kii) * BS + b) * (2 * DIMM) + h * HD + kcb;
        const char* gK = (const char*)(KV + koff);
        const char* gV = (const char*)(KV + koff + DIMM);
        const uint32_t d = smem_u32(st) + kii * 144 + (tid & 3) * 32;
        CPA(d,          gK);  CPA(d + 16,          gK + 16);
        CPA(d + 9216,   gV);  CPA(d + 9216 + 16,   gV + 16);
        CPC();
    };

    issue_kv(jb);
    {
        const int qi = tid >> 1, qc = (tid & 1) * 32;
        const size_t qoff = (size_t)((i0 + qi) * BS + b) * DIMM + h * HD + qc;
        #pragma unroll
        for (int q = 0; q < 4; q++) {
            *(uint4*)&Qh_s[qi][qc + q * 8] = *(const uint4*)&Quh[qoff + q * 8];
            *(uint4*)&Ql_s[qi][qc + q * 8] = *(const uint4*)&Qul[qoff + q * 8];
        }
    }
    __syncthreads();

    uint32_t qh[4][4], ql[4][4];
    #pragma unroll
    for (int s = 0; s < 4; s++) {
        int rowi = w * 16 + (lane & 15);
        int kc  = s * 16 + ((lane & 16) >> 1);
        ldsm4(qh[s], smem_u32(&Qh_s[rowi][kc]));
        ldsm4(ql[s], smem_u32(&Ql_s[rowi][kc]));
    }

    float oacc[8][4] = {};
    float m0 = -1e30f, m1 = -1e30f, l0 = 0.f, l1 = 0.f;

    const int irow0 = i0 + w * 16 + r;
    const int jlimit = i0 + w * 16 + 15 + PREV;
    const float* c2row0 = C2 + ((size_t)bh * CUR + irow0) * FULL;
    const float* c2row1 = c2row0 + (size_t)8 * FULL;

    for (int jt = jb; jt < je; jt++) {
        const int j0 = jt * 64;
        CPW(0);
        __syncthreads();
        if (jt + 1 < je) issue_kv(jt + 1);

        if (j0 <= jlimit) {
        char* st = dsm + (jt & 1) * ASTAGE;
        hf* K_s = (hf*)st;
        hf* V_s = (hf*)(st + 9216);

        float sacc[8][4] = {};
        #pragma unroll
        for (int s = 0; s < 4; s++) {
            const int ks = s * 16;
            uint32_t bhf[8][2];
            #pragma unroll
            for (int g4 = 0; g4 < 4; g4++) {
                int nrow = g4 * 16 + (lane & 15);
                int kc   = ks + ((lane & 16) >> 1);
                uint32_t t[4];
                ldsm4(t, smem_u32(&K_s[nrow * 72 + kc]));
                bhf[2*g4][0] = t[0]; bhf[2*g4+1][0] = t[1];
                bhf[2*g4][1] = t[2]; bhf[2*g4+1][1] = t[3];
            }
            #pragma unroll
            for (int g = 0; g < 8; g++) {
                mmah(sacc[g], qh[s], bhf[g]);
                mmah(sacc[g], ql[s], bhf[g]);
            }
        }

        const bool need_mask = (j0 + 63 > irow0 + PREV);
        #pragma unroll
        for (int g = 0; g < 8; g++) {
            int jg  = j0 + g * 8 + 2 * cq;
            int k00 = jg - irow0 + 511;
            int k10 = k00 - 8;
            if (!need_mask) {
                sacc[g][0] += c2row0[k00];
                sacc[g][1] += c2row0[k00 + 1];
                sacc[g][2] += c2row1[k10];
                sacc[g][3] += c2row1[k10 + 1];
            } else {
                sacc[g][0] = (k00     <= 1023) ? sacc[g][0] + c2row0[k00]     : -1e30f;
                sacc[g][1] = (k00 + 1 <= 1023) ? sacc[g][1] + c2row0[k00 + 1] : -1e30f;
                sacc[g][2] = (k10     <= 1023) ? sacc[g][2] + c2row1[k10]     : -1e30f;
                sacc[g][3] = (k10 + 1 <= 1023) ? sacc[g][3] + c2row1[k10 + 1] : -1e30f;
            }
        }

        float mx0 = -1e30f, mx1 = -1e30f;
        #pragma unroll
        for (int g = 0; g < 8; g++) {
            mx0 = fmaxf(mx0, fmaxf(sacc[g][0], sacc[g][1]));
            mx1 = fmaxf(mx1, fmaxf(sacc[g][2], sacc[g][3]));
        }
        mx0 = fmaxf(mx0, __shfl_xor_sync(0xffffffffu, mx0, 1));
        mx0 = fmaxf(mx0, __shfl_xor_sync(0xffffffffu, mx0, 2));
        mx1 = fmaxf(mx1, __shfl_xor_sync(0xffffffffu, mx1, 1));
        mx1 = fmaxf(mx1, __shfl_xor_sync(0xffffffffu, mx1, 2));

        float mn0 = fmaxf(m0, mx0), mn1 = fmaxf(m1, mx1);
        float a0 = __expf(m0 - mn0), a1 = __expf(m1 - mn1);
        m0 = mn0; m1 = mn1;
        l0 *= a0; l1 *= a1;
        #pragma unroll
        for (int g = 0; g < 8; g++) {
            oacc[g][0] *= a0; oacc[g][1] *= a0;
            oacc[g][2] *= a1; oacc[g][3] *= a1;
        }

        uint32_t pah[4][4], pal[4][4];
        #pragma unroll
        for (int t4 = 0; t4 < 4; t4++) {
            #pragma unroll
            for (int gg = 0; gg < 2; gg++) {
                int g = 2 * t4 + gg;
                float p0 = __expf(sacc[g][0] - m0);
                float p1 = __expf(sacc[g][1] - m0);
                float p2 = __expf(sacc[g][2] - m1);
                float p3 = __expf(sacc[g][3] - m1);
                l0 += p0 + p1;
                l1 += p2 + p3;
                split2h(p0, p1, pah[t4][2*gg],     pal[t4][2*gg]);
                split2h(p2, p3, pah[t4][2*gg + 1], pal[t4][2*gg + 1]);
            }
        }

        #pragma unroll
        for (int t4 = 0; t4 < 4; t4++) {
            uint32_t vhf[8][2];
            #pragma unroll
            for (int g4 = 0; g4 < 4; g4++) {
                int krow = t4 * 16 + (lane & 15);
                int ncc  = g4 * 16 + ((lane & 16) >> 1);
                uint32_t t[4];
                ldsm4t(t, smem_u32(&V_s[krow * 72 + ncc]));
                vhf[2*g4][0] = t[0]; vhf[2*g4][1] = t[1];
                vhf[2*g4+1][0] = t[2]; vhf[2*g4+1][1] = t[3];
            }
            #pragma unroll
            for (int g = 0; g < 8; g++) {
                mmah(oacc[g], pah[t4], vhf[g]);
                mmah(oacc[g], pal[t4], vhf[g]);
            }
        }
        } // j0 <= jlimit
    }

    l0 += __shfl_xor_sync(0xffffffffu, l0, 1);
    l0 += __shfl_xor_sync(0xffffffffu, l0, 2);
    l1 += __shfl_xor_sync(0xffffffffu, l1, 1);
    l1 += __shfl_xor_sync(0xffffffffu, l1, 2);

    const size_t pbase = ((size_t)(jhalf * 64 + bh)) * CUR;
    if (cq == 0) {
        Pm[pbase + irow0]     = m0;  Pl[pbase + irow0]     = l0;
        Pm[pbase + irow0 + 8] = m1;  Pl[pbase + irow0 + 8] = l1;
    }
    float* po0 = PO + (pbase + irow0) * 64;
    float* po1 = PO + (pbase + irow0 + 8) * 64;
    #pragma unroll
    for (int g = 0; g < 8; g++) {
        int col = g * 8 + 2 * cq;
        *(float2*)&po0[col] = make_float2(oacc[g][0], oacc[g][1]);
        *(float2*)&po1[col] = make_float2(oacc[g][2], oacc[g][3]);
    }
}

// ---------------------------------------------------------------------------
// Split-KV combine -> AV (split fp16)
// ---------------------------------------------------------------------------
__global__ __launch_bounds__(256)
void attn_combine(const float* __restrict__ PO, const float* __restrict__ Pm,
                  const float* __restrict__ Pl,
                  hf* __restrict__ AVh, hf* __restrict__ AVl)
{
    const int t = blockIdx.x * 256 + threadIdx.x;
    const int bh = t >> 12;
    const int rem = t & 4095;
    const int row = rem >> 3;
    const int colg = (rem & 7) * 8;
    const int b = bh >> 4, h = bh & 15;

    const size_t r0 = (size_t)bh * CUR + row;
    const size_t r1 = (size_t)(64 + bh) * CUR + row;
    const float m0 = Pm[r0], m1 = Pm[r1];
    const float l0 = Pl[r0], l1 = Pl[r1];
    const float ms = fmaxf(m0, m1);
    const float f0 = __expf(m0 - ms), f1 = __expf(m1 - ms);
    const float inv = 1.f / (l0 * f0 + l1 * f1);

    const float* po0 = PO + r0 * 64 + colg;
    const float* po1 = PO + r1 * 64 + colg;
    hf* oh = AVh + (size_t)(row * BS + b) * DIMM + h * HD + colg;
    hf* ol = AVl + (size_t)(row * BS + b) * DIMM + h * HD + colg;

    #pragma unroll
    for (int c = 0; c < 8; c += 2) {
        float2 a = *(const float2*)&po0[c];
        float2 d = *(const float2*)&po1[c];
        float x = (a.x * f0 + d.x * f1) * inv;
        float y = (a.y * f0 + d.y * f1) * inv;
        store_split_h(&oh[c], &ol[c], x, y);
    }
}

// ---------------------------------------------------------------------------
// Launch
// ---------------------------------------------------------------------------
extern "C" void kernel_launch(void* const* d_in, const int* in_sizes, int n_in,
                              void* d_out, int out_size)
{
    const float* inputs  = (const float*)d_in[0];
    const float* pos_emb = (const float*)d_in[1];
    const float* full_in = (const float*)d_in[2];
    const float* u       = (const float*)d_in[3];
    const float* v       = (const float*)d_in[4];
    const float* W_kv    = (const float*)d_in[5];
    const float* b_kv    = (const float*)d_in[6];
    const float* W_q     = (const float*)d_in[7];
    const float* b_q     = (const float*)d_in[8];
    const float* W_pos   = (const float*)d_in[9];
    const float* b_pos   = (const float*)d_in[10];
    const float* W_proj  = (const float*)d_in[11];
    const float* b_proj  = (const float*)d_in[12];
    float* out = (float*)d_out;

    hf *FIh, *FIl, *INh, *INl, *PEh, *PEl, *Wkv, *Wq, *Wp, *Wpr,
       *KV, *Quh, *Qul, *Qvh, *Qvl, *R, *AVh, *AVl;
    float *C2, *PO, *Pm, *Pl;
    cudaGetSymbolAddress((void**)&FIh, g_FIh);   cudaGetSymbolAddress((void**)&FIl, g_FIl);
    cudaGetSymbolAddress((void**)&INh, g_INh);   cudaGetSymbolAddress((void**)&INl, g_INl);
    cudaGetSymbolAddress((void**)&PEh, g_PEh);   cudaGetSymbolAddress((void**)&PEl, g_PEl);
    cudaGetSymbolAddress((void**)&Wkv, g_Wkv);   cudaGetSymbolAddress((void**)&Wq, g_Wq);
    cudaGetSymbolAddress((void**)&Wp, g_Wp);     cudaGetSymbolAddress((void**)&Wpr, g_Wpr);
    cudaGetSymbolAddress((void**)&KV, g_KV);
    cudaGetSymbolAddress((void**)&Quh, g_Quh);   cudaGetSymbolAddress((void**)&Qul, g_Qul);
    cudaGetSymbolAddress((void**)&Qvh, g_Qvh);   cudaGetSymbolAddress((void**)&Qvl, g_Qvl);
    cudaGetSymbolAddress((void**)&R, g_R);
    cudaGetSymbolAddress((void**)&AVh, g_AVh);   cudaGetSymbolAddress((void**)&AVl, g_AVl);
    cudaGetSymbolAddress((void**)&C2, g_C2);
    cudaGetSymbolAddress((void**)&PO, g_PO);
    cudaGetSymbolAddress((void**)&Pm, g_Pm);
    cudaGetSymbolAddress((void**)&Pl, g_Pl);

    const int GSM = 4 * GSTAGE;     // 116736
    const int ASM = 2 * ASTAGE;     // 36864
    cudaFuncSetAttribute(gemm_mega, cudaFuncAttributeMaxDynamicSharedMemorySize, GSM);
    cudaFuncSetAttribute(attn_ca,   cudaFuncAttributeMaxDynamicSharedMemorySize, ASM);

    // 1. All conversions in one grid
    CT ct;
    ct.s[0] = full_in; ct.h[0] = FIh; ct.l[0] = FIl; ct.md[0] = 1;
    ct.s[1] = inputs;  ct.h[1] = INh; ct.l[1] = INl; ct.md[1] = 1;
    ct.s[2] = pos_emb; ct.h[2] = PEh; ct.l[2] = PEl; ct.md[2] = 1;
    ct.s[3] = W_kv;    ct.h[3] = Wkv; ct.l[3] = nullptr; ct.md[3] = 0;
    ct.s[4] = W_q;     ct.h[4] = Wq;  ct.l[4] = nullptr; ct.md[4] = 0;
    ct.s[5] = W_pos;   ct.h[5] = Wp;  ct.l[5] = nullptr; ct.md[5] = 0;
    ct.s[6] = W_proj;  ct.h[6] = Wpr; ct.l[6] = nullptr; ct.md[6] = 0;
    ct.end[0] = 4096;  ct.end[1] = 6144;  ct.end[2] = 7168;
    ct.end[3] = 9216;  ct.end[4] = 10240; ct.end[5] = 11264; ct.end[6] = 12288;
    cvt_mega<<<12288, 256>>>(ct);

    // 2. Mega GEMM {KV(single out), Q(dual split, x0.125), R(single out)}
    GT3 ts;
    ts.t[0] = { FIh, FIl, Wkv, b_kv, nullptr, nullptr,
                nullptr, KV, nullptr, nullptr, nullptr, 2048, 1024, 16, 1 };
    ts.t[1] = { INh, INl, Wq, b_q, u, v,
                nullptr, Quh, Qul, Qvh, Qvl, 1024, 1024, 8, 2 };
    ts.t[2] = { PEh, PEl, Wp, b_pos, nullptr, nullptr,
                nullptr, R, nullptr, nullptr, nullptr, 1024, 1024, 8, 1 };
    ts.end0 = 512; ts.end1 = 640;
    gemm_mega<<<704, 256, GSM>>>(ts);

    // 3. Position scores
    pos_scores_bb<<<dim3(FULL / 64, CUR / 64, BS * NH), 128>>>(Qvh, Qvl, R, C2);

    // 4a. Fused attention, split-KV (partials)
    attn_ca<<<dim3(8, BS * NH), 256, ASM>>>(Quh, Qul, KV, C2, PO, Pm, Pl);

    // 4b. Combine partials -> AV (split fp16)
    attn_combine<<<(64 * 512 * 8) / 256, 256>>>(PO, Pm, Pl, AVh, AVl);

    // 5. out = AV @ W_proj + b_proj (fp32)
    GT3 tp;
    tp.t[0] = { AVh, AVl, Wpr, b_proj, nullptr, nullptr,
                out, nullptr, nullptr, nullptr, nullptr, 1024, 1024, 8, 0 };
    tp.t[1] = tp.t[0]; tp.t[2] = tp.t[0];
    tp.end0 = 128; tp.end1 = 128;
    gemm_mega<<<128, 256, GSM>>>(tp);
}

// round 17
// speedup vs baseline: 1.4743x; 1.0749x over previous
#include <cuda_runtime.h>
#include <cuda_fp16.h>
#include <cstdint>
#include <cstddef>

#define CUR   512
#define FULL  1024
#define BS    4
#define DIMM  1024
#define NH    16
#define HD    64
#define PREV  512

typedef __half hf;

// ---------------- scratch ----------------
__device__ __align__(256) hf g_FIh[4194304], g_FIl[4194304];
__device__ __align__(256) hf g_INh[2097152], g_INl[2097152];
__device__ __align__(256) hf g_PEh[1048576], g_PEl[1048576];
__device__ __align__(256) hf g_Wkv[2097152];
__device__ __align__(256) hf g_Wq[1048576];
__device__ __align__(256) hf g_Wp[1048576];
__device__ __align__(256) hf g_Wpr[1048576];
__device__ __align__(256) hf g_KV[8388608];                    // (4096,2048) K|V single
__device__ __align__(256) hf g_Qu[2097152];                    // 0.125*(Q+u) single
__device__ __align__(256) hf g_Qvh[2097152], g_Qvl[2097152];   // 0.125*(Q+v) split
__device__ __align__(256) hf g_R[1048576];                     // single
__device__ __align__(256) hf g_AVh[2097152], g_AVl[2097152];   // split
__device__ __align__(256) hf g_C2h[(size_t)BS * NH * CUR * FULL + 512];  // fp16 scores (+pad)
__device__ float g_PO[4194304];
__device__ float g_Pm[65536];
__device__ float g_Pl[65536];

// ---------------- helpers ----------------
__device__ __forceinline__ uint32_t smem_u32(const void* p) {
    return (uint32_t)__cvta_generic_to_shared(p);
}
__device__ __forceinline__ void ldsm4(uint32_t* r, uint32_t a) {
    asm volatile("ldmatrix.sync.aligned.m8n8.x4.shared.b16 {%0,%1,%2,%3}, [%4];"
        : "=r"(r[0]), "=r"(r[1]), "=r"(r[2]), "=r"(r[3]) : "r"(a));
}
__device__ __forceinline__ void ldsm4t(uint32_t* r, uint32_t a) {
    asm volatile("ldmatrix.sync.aligned.m8n8.x4.trans.shared.b16 {%0,%1,%2,%3}, [%4];"
        : "=r"(r[0]), "=r"(r[1]), "=r"(r[2]), "=r"(r[3]) : "r"(a));
}
__device__ __forceinline__ void mmah(float* d, const uint32_t* a, const uint32_t* b) {
    asm volatile(
        "mma.sync.aligned.m16n8k16.row.col.f32.f16.f16.f32 "
        "{%0,%1,%2,%3},{%4,%5,%6,%7},{%8,%9},{%0,%1,%2,%3};"
        : "+f"(d[0]), "+f"(d[1]), "+f"(d[2]), "+f"(d[3])
        : "r"(a[0]), "r"(a[1]), "r"(a[2]), "r"(a[3]), "r"(b[0]), "r"(b[1]));
}
__device__ __forceinline__ void sth2(hf* p, float x, float y) {
    __half2 t; t.x = __float2half_rn(x); t.y = __float2half_rn(y);
    *(__half2*)p = t;
}
__device__ __forceinline__ void store_split_h(hf* ph, hf* pl, float x, float y) {
    hf hx = __float2half_rn(x), hy = __float2half_rn(y);
    __half2 H; H.x = hx; H.y = hy;
    __half2 L;
    L.x = __float2half_rn(x - __half2float(hx));
    L.y = __float2half_rn(y - __half2float(hy));
    *(__half2*)ph = H;
    *(__half2*)pl = L;
}
__device__ __forceinline__ uint32_t pack2h(float x, float y) {
    __half2 H; H.x = __float2half_rn(x); H.y = __float2half_rn(y);
    return *reinterpret_cast<uint32_t*>(&H);
}
#define CPA(dst, src) \
    asm volatile("cp.async.cg.shared.global [%0], [%1], 16;" :: "r"(dst), "l"(src))
#define CPC() asm volatile("cp.async.commit_group;" ::: "memory")
#define CPW(n) asm volatile("cp.async.wait_group %0;" :: "n"(n) : "memory")
__device__ __forceinline__ void cpw_rem(int rem) {
    if (rem >= 2) CPW(2);
    else if (rem == 1) CPW(1);
    else CPW(0);
}

// ---------------- merged converter ----------------
struct CT {
    const float* s[7];
    hf* h[7];
    hf* l[7];
    int end[7];
    int md[7];
};
__global__ __launch_bounds__(256)
void cvt_mega(CT c)
{
    const int bid = blockIdx.x;
    int ti = 0;
    #pragma unroll
    for (int k = 0; k < 6; k++) ti += (bid >= c.end[k]) ? 1 : 0;
    const int base = ti ? c.end[ti - 1] : 0;
    const int i = ((bid - base) * 256 + threadIdx.x) * 4;
    float4 v = *(const float4*)&c.s[ti][i];
    if (c.md[ti]) {
        store_split_h(&c.h[ti][i],     &c.l[ti][i],     v.x, v.y);
        store_split_h(&c.h[ti][i + 2], &c.l[ti][i + 2], v.z, v.w);
    } else {
        sth2(&c.h[ti][i],     v.x, v.y);
        sth2(&c.h[ti][i + 2], v.z, v.w);
    }
}

// ---------------------------------------------------------------------------
// Mega GEMM: C = A(split fp16) * B(single fp16) (+bias). 128x128, BK=32,
// 256 thr, 2-mma/product, 4-stage cp.async.
// mode 0: fp32 out. mode 1: single fp16 out.
// mode 2: Qu single 0.125*(+u) -> Xh; Qv split 0.125*(+v) -> Yh/Yl.
// ---------------------------------------------------------------------------
struct GTask {
    const hf *Ah, *Al, *B;
    const float *bias, *uvec, *vvec;
    float* Cf;
    hf *Xh, *Xl, *Yh, *Yl;
    int N, K, nbx, mode;
};
struct GT3 { GTask t[3]; int end0, end1; };

#define GSTAGE 29184
__global__ __launch_bounds__(256)
void gemm_mega(GT3 ts)
{
    extern __shared__ char dsm[];
    const int bid = blockIdx.x;
    const int ti = (bid >= ts.end0 ? 1 : 0) + (bid >= ts.end1 ? 1 : 0);
    const GTask T = ts.t[ti];
    const int base = (ti == 0) ? 0 : (ti == 1 ? ts.end0 : ts.end1);
    const int local = bid - base;
    const int by = local / T.nbx, bx = local - by * T.nbx;

    const int tid = threadIdx.x, lane = tid & 31, wid = tid >> 5;
    const int wm = wid >> 1, wn = wid & 1;
    const int m0 = by * 128, n0 = bx * 128;
    const int N = T.N, K = T.K;

    const int lam = tid >> 1, lac = (tid & 1) * 16;
    const int lbk = tid >> 3, lbn = (tid & 7) * 16;

    const hf* gAh = T.Ah + (size_t)(m0 + lam) * K + lac;
    const hf* gAl = T.Al + (size_t)(m0 + lam) * K + lac;
    const hf* gB  = T.B  + (size_t)lbk * N + n0 + lbn;

    const uint32_t dA0 = smem_u32(dsm) + lam * 80 + (tid & 1) * 32;
    const uint32_t dB0 = smem_u32(dsm) + 20480 + lbk * 272 + (tid & 7) * 32;

    const int nc = K / 32;

    auto issue = [&](int t) {
        const int s = t & 3;
        const uint32_t da = dA0 + s * GSTAGE;
        const uint32_t db = dB0 + s * GSTAGE;
        const hf* ah = gAh + t * 32;
        const hf* al = gAl + t * 32;
        const hf* bb = gB + (size_t)t * 32 * N;
        CPA(da,         ah);  CPA(da + 16,         ah + 8);
        CPA(da + 10240, al);  CPA(da + 10240 + 16, al + 8);
        CPA(db,         bb);  CPA(db + 16,         bb + 8);
        CPC();
    };

    issue(0); issue(1); issue(2);

    float acc[2][8][4] = {};

    for (int t = 0; t < nc; t++) {
        cpw_rem(nc - 1 - t);
        __syncthreads();
        if (t + 3 < nc) issue(t + 3);

        char* st = dsm + (t & 3) * GSTAGE;
        hf* sAh = (hf*)st;
        hf* sAl = (hf*)(st + 10240);
        hf* sB  = (hf*)(st + 20480);

        #pragma unroll
        for (int s = 0; s < 2; s++) {
            const int ks = s * 16;
            uint32_t ahf[2][4], alf[2][4], bhf[8][2];
            #pragma unroll
            for (int f = 0; f < 2; f++) {
                int row = wm * 32 + f * 16 + (lane & 15);
                int kc  = ks + ((lane & 16) >> 1);
                ldsm4(ahf[f], smem_u32(&sAh[row * 40 + kc]));
                ldsm4(alf[f], smem_u32(&sAl[row * 40 + kc]));
            }
            #pragma unroll
            for (int g4 = 0; g4 < 4; g4++) {
                int krow = ks + (lane & 15);
                int ncc  = wn * 64 + g4 * 16 + ((lane & 16) >> 1);
                uint32_t tt[4];
                ldsm4t(tt, smem_u32(&sB[krow * 136 + ncc]));
                bhf[2*g4][0] = tt[0]; bhf[2*g4][1] = tt[1];
                bhf[2*g4+1][0] = tt[2]; bhf[2*g4+1][1] = tt[3];
            }
            #pragma unroll
            for (int f = 0; f < 2; f++)
                #pragma unroll
                for (int g = 0; g < 8; g++) {
                    mmah(acc[f][g], ahf[f], bhf[g]);
                    mmah(acc[f][g], alf[f], bhf[g]);
                }
        }
    }

    const int r = lane >> 2, c2 = (lane & 3) * 2;
    #pragma unroll
    for (int f = 0; f < 2; f++) {
        int row0 = m0 + wm * 32 + f * 16 + r;
        #pragma unroll
        for (int g = 0; g < 8; g++) {
            int col = n0 + wn * 64 + g * 8 + c2;
            float2 b2 = *(const float2*)&T.bias[col];
            float v00 = acc[f][g][0] + b2.x, v01 = acc[f][g][1] + b2.y;
            float v10 = acc[f][g][2] + b2.x, v11 = acc[f][g][3] + b2.y;
            size_t i0o = (size_t)row0 * N + col;
            size_t i1o = (size_t)(row0 + 8) * N + col;
            if (T.mode == 0) {
                *(float2*)&T.Cf[i0o] = make_float2(v00, v01);
                *(float2*)&T.Cf[i1o] = make_float2(v10, v11);
            } else if (T.mode == 1) {
                sth2(&T.Xh[i0o], v00, v01);
                sth2(&T.Xh[i1o], v10, v11);
            } else {
                float2 uu = *(const float2*)&T.uvec[col];
                float2 vv = *(const float2*)&T.vvec[col];
                sth2(&T.Xh[i0o], 0.125f*(v00 + uu.x), 0.125f*(v01 + uu.y));
                sth2(&T.Xh[i1o], 0.125f*(v10 + uu.x), 0.125f*(v11 + uu.y));
                store_split_h(&T.Yh[i0o], &T.Yl[i0o], 0.125f*(v00 + vv.x), 0.125f*(v01 + vv.y));
                store_split_h(&T.Yh[i1o], &T.Yl[i1o], 0.125f*(v10 + vv.x), 0.125f*(v11 + vv.y));
            }
        }
    }
}

// ---------------------------------------------------------------------------
// Position scores: C2h(fp16) = Qv(split) . R(single), 2-mma. 64x64 tile.
// ---------------------------------------------------------------------------
__global__ __launch_bounds__(128)
void pos_scores_bb(const hf* __restrict__ Qvh, const hf* __restrict__ Qvl,
                   const hf* __restrict__ R, hf* __restrict__ C2)
{
    const int bh = blockIdx.z, b = bh >> 4, h = bh & 15;
    const int i0 = blockIdx.y * 64, n0 = blockIdx.x * 64;
    if (n0 + i0 < 385) return;

    __shared__ hf sQh[64][72], sQl[64][72], sR[64][72];

    const int tid = threadIdx.x, lane = tid & 31, wid = tid >> 5;
    const int wm = wid >> 1, wn = wid & 1;

    {
        const int row = tid >> 1, cb = (tid & 1) * 32;
        const size_t qoff = (size_t)((i0 + row) * BS + b) * DIMM + h * HD + cb;
        const size_t roff = (size_t)(n0 + row) * DIMM + h * HD + cb;
        #pragma unroll
        for (int q = 0; q < 4; q++) {
            *(uint4*)&sQh[row][cb + q * 8] = *(const uint4*)&Qvh[qoff + q * 8];
            *(uint4*)&sQl[row][cb + q * 8] = *(const uint4*)&Qvl[qoff + q * 8];
            *(uint4*)&sR[row][cb + q * 8]  = *(const uint4*)&R[roff + q * 8];
        }
    }
    __syncthreads();

    float acc[2][4][4] = {};
    #pragma unroll
    for (int s = 0; s < 4; s++) {
        const int ks = s * 16;
        uint32_t ah[2][4], al[2][4], bh2[4][2];
        #pragma unroll
        for (int f = 0; f < 2; f++) {
            int row = wm * 32 + f * 16 + (lane & 15);
            int kc  = ks + ((lane & 16) >> 1);
            ldsm4(ah[f], smem_u32(&sQh[row][kc]));
            ldsm4(al[f], smem_u32(&sQl[row][kc]));
        }
        #pragma unroll
        for (int g4 = 0; g4 < 2; g4++) {
            int nrow = wn * 32 + g4 * 16 + (lane & 15);
            int kc   = ks + ((lane & 16) >> 1);
            uint32_t t[4];
            ldsm4(t, smem_u32(&sR[nrow][kc]));
            bh2[2*g4][0] = t[0]; bh2[2*g4+1][0] = t[1];
            bh2[2*g4][1] = t[2]; bh2[2*g4+1][1] = t[3];
        }
        #pragma unroll
        for (int f = 0; f < 2; f++)
            #pragma unroll
            for (int g = 0; g < 4; g++) {
                mmah(acc[f][g], ah[f], bh2[g]);
                mmah(acc[f][g], al[f], bh2[g]);
            }
    }

    const int r = lane >> 2, c2 = (lane & 3) * 2;
    hf* out = C2 + (size_t)bh * CUR * FULL;
    #pragma unroll
    for (int f = 0; f < 2; f++) {
        int row0 = i0 + wm * 32 + f * 16 + r;
        #pragma unroll
        for (int g = 0; g < 4; g++) {
            int col = n0 + wn * 32 + g * 8 + c2;
            sth2(&out[(size_t)row0 * FULL + col],       acc[f][g][0], acc[f][g][1]);
            sth2(&out[(size_t)(row0 + 8) * FULL + col], acc[f][g][2], acc[f][g][3]);
        }
    }
}

// ---------------------------------------------------------------------------
// Fused attention, split-KV. Q single fp16, K/V single fp16, P single fp16:
// 1 mma per product (64 mma/tile). grid (8, 64). Partials fp32.
// ---------------------------------------------------------------------------
#define ASTAGE 18432
__global__ __launch_bounds__(256, 2)
void attn_ca(const hf* __restrict__ Qu, const hf* __restrict__ KV,
             const hf* __restrict__ C2,
             float* __restrict__ PO, float* __restrict__ Pm,
             float* __restrict__ Pl)
{
    extern __shared__ char dsm[];
    __shared__ hf Qh_s[128][72];

    const int i0blk = blockIdx.x >> 1, jhalf = blockIdx.x & 1;
    const int bh = blockIdx.y, b = bh >> 4, h = bh & 15;
    const int i0 = i0blk * 128;

    const int tid = threadIdx.x, lane = tid & 31, w = tid >> 5;
    const int r = lane >> 2, cq = lane & 3;

    const int jtiles = i0 / 64 + 10;
    const int jhalf0 = jtiles >> 1;
    const int jb = jhalf ? jhalf0 : 0;
    const int je = jhalf ? jtiles : jhalf0;

    const int kii = tid >> 2, kcb = (tid & 3) * 16;
    auto issue_kv = [&](int jt) {
        char* st = dsm + (jt & 1) * ASTAGE;
        const size_t koff = (size_t)((jt * 64 + kii) * BS + b) * (2 * DIMM) + h * HD + kcb;
        const char* gK = (const char*)(KV + koff);
        const char* gV = (const char*)(KV + koff + DIMM);
        const uint32_t d = smem_u32(st) + kii * 144 + (tid & 3) * 32;
        CPA(d,          gK);  CPA(d + 16,          gK + 16);
        CPA(d + 9216,   gV);  CPA(d + 9216 + 16,   gV + 16);
        CPC();
    };

    issue_kv(jb);
    {
        const int qi = tid >> 1, qc = (tid & 1) * 32;
        const size_t qoff = (size_t)((i0 + qi) * BS + b) * DIMM + h * HD + qc;
        #pragma unroll
        for (int q = 0; q < 4; q++)
            *(uint4*)&Qh_s[qi][qc + q * 8] = *(const uint4*)&Qu[qoff + q * 8];
    }
    __syncthreads();

    uint32_t qh[4][4];
    #pragma unroll
    for (int s = 0; s < 4; s++) {
        int rowi = w * 16 + (lane & 15);
        int kc  = s * 16 + ((lane & 16) >> 1);
        ldsm4(qh[s], smem_u32(&Qh_s[rowi][kc]));
    }

    float oacc[8][4] = {};
    float m0 = -1e30f, m1 = -1e30f, l0 = 0.f, l1 = 0.f;

    const int irow0 = i0 + w * 16 + r;
    const int jlimit = i0 + w * 16 + 15 + PREV;
    const hf* c2row0 = C2 + ((size_t)bh * CUR + irow0) * FULL;
    const hf* c2row1 = c2row0 + (size_t)8 * FULL;

    for (int jt = jb; jt < je; jt++) {
        const int j0 = jt * 64;
        CPW(0);
        __syncthreads();
        if (jt + 1 < je) issue_kv(jt + 1);

        if (j0 <= jlimit) {
        char* st = dsm + (jt & 1) * ASTAGE;
        hf* K_s = (hf*)st;
        hf* V_s = (hf*)(st + 9216);

        float sacc[8][4] = {};
        #pragma unroll
        for (int s = 0; s < 4; s++) {
            const int ks = s * 16;
            uint32_t bhf[8][2];
            #pragma unroll
            for (int g4 = 0; g4 < 4; g4++) {
                int nrow = g4 * 16 + (lane & 15);
                int kc   = ks + ((lane & 16) >> 1);
                uint32_t t[4];
                ldsm4(t, smem_u32(&K_s[nrow * 72 + kc]));
                bhf[2*g4][0] = t[0]; bhf[2*g4+1][0] = t[1];
                bhf[2*g4][1] = t[2]; bhf[2*g4+1][1] = t[3];
            }
            #pragma unroll
            for (int g = 0; g < 8; g++)
                mmah(sacc[g], qh[s], bhf[g]);
        }

        const bool need_mask = (j0 + 63 > irow0 + PREV);
        #pragma unroll
        for (int g = 0; g < 8; g++) {
            int jg  = j0 + g * 8 + 2 * cq;
            int k00 = jg - irow0 + 511;
            int k10 = k00 - 8;
            if (!need_mask) {
                sacc[g][0] += __half2float(c2row0[k00]);
                sacc[g][1] += __half2float(c2row0[k00 + 1]);
                sacc[g][2] += __half2float(c2row1[k10]);
                sacc[g][3] += __half2float(c2row1[k10 + 1]);
            } else {
                sacc[g][0] = (k00     <= 1023) ? sacc[g][0] + __half2float(c2row0[k00])     : -1e30f;
                sacc[g][1] = (k00 + 1 <= 1023) ? sacc[g][1] + __half2float(c2row0[k00 + 1]) : -1e30f;
                sacc[g][2] = (k10     <= 1023) ? sacc[g][2] + __half2float(c2row1[k10])     : -1e30f;
                sacc[g][3] = (k10 + 1 <= 1023) ? sacc[g][3] + __half2float(c2row1[k10 + 1]) : -1e30f;
            }
        }

        float mx0 = -1e30f, mx1 = -1e30f;
        #pragma unroll
        for (int g = 0; g < 8; g++) {
            mx0 = fmaxf(mx0, fmaxf(sacc[g][0], sacc[g][1]));
            mx1 = fmaxf(mx1, fmaxf(sacc[g][2], sacc[g][3]));
        }
        mx0 = fmaxf(mx0, __shfl_xor_sync(0xffffffffu, mx0, 1));
        mx0 = fmaxf(mx0, __shfl_xor_sync(0xffffffffu, mx0, 2));
        mx1 = fmaxf(mx1, __shfl_xor_sync(0xffffffffu, mx1, 1));
        mx1 = fmaxf(mx1, __shfl_xor_sync(0xffffffffu, mx1, 2));

        float mn0 = fmaxf(m0, mx0), mn1 = fmaxf(m1, mx1);
        float a0 = __expf(m0 - mn0), a1 = __expf(m1 - mn1);
        m0 = mn0; m1 = mn1;
        l0 *= a0; l1 *= a1;
        #pragma unroll
        for (int g = 0; g < 8; g++) {
            oacc[g][0] *= a0; oacc[g][1] *= a0;
            oacc[g][2] *= a1; oacc[g][3] *= a1;
        }

        uint32_t pah[4][4];
        #pragma unroll
        for (int t4 = 0; t4 < 4; t4++) {
            #pragma unroll
            for (int gg = 0; gg < 2; gg++) {
                int g = 2 * t4 + gg;
                float p0 = __expf(sacc[g][0] - m0);
                float p1 = __expf(sacc[g][1] - m0);
                float p2 = __expf(sacc[g][2] - m1);
                float p3 = __expf(sacc[g][3] - m1);
                l0 += p0 + p1;
                l1 += p2 + p3;
                pah[t4][2*gg]     = pack2h(p0, p1);
                pah[t4][2*gg + 1] = pack2h(p2, p3);
            }
        }

        #pragma unroll
        for (int t4 = 0; t4 < 4; t4++) {
            uint32_t vhf[8][2];
            #pragma unroll
            for (int g4 = 0; g4 < 4; g4++) {
                int krow = t4 * 16 + (lane & 15);
                int ncc  = g4 * 16 + ((lane & 16) >> 1);
                uint32_t t[4];
                ldsm4t(t, smem_u32(&V_s[krow * 72 + ncc]));
                vhf[2*g4][0] = t[0]; vhf[2*g4][1] = t[1];
                vhf[2*g4+1][0] = t[2]; vhf[2*g4+1][1] = t[3];
            }
            #pragma unroll
            for (int g = 0; g < 8; g++)
                mmah(oacc[g], pah[t4], vhf[g]);
        }
        } // j0 <= jlimit
    }

    l0 += __shfl_xor_sync(0xffffffffu, l0, 1);
    l0 += __shfl_xor_sync(0xffffffffu, l0, 2);
    l1 += __shfl_xor_sync(0xffffffffu, l1, 1);
    l1 += __shfl_xor_sync(0xffffffffu, l1, 2);

    const size_t pbase = ((size_t)(jhalf * 64 + bh)) * CUR;
    if (cq == 0) {
        Pm[pbase + irow0]     = m0;  Pl[pbase + irow0]     = l0;
        Pm[pbase + irow0 + 8] = m1;  Pl[pbase + irow0 + 8] = l1;
    }
    float* po0 = PO + (pbase + irow0) * 64;
    float* po1 = PO + (pbase + irow0 + 8) * 64;
    #pragma unroll
    for (int g = 0; g < 8; g++) {
        int col = g * 8 + 2 * cq;
        *(float2*)&po0[col] = make_float2(oacc[g][0], oacc[g][1]);
        *(float2*)&po1[col] = make_float2(oacc[g][2], oacc[g][3]);
    }
}

// ---------------------------------------------------------------------------
// Split-KV combine -> AV (split fp16)
// ---------------------------------------------------------------------------
__global__ __launch_bounds__(256)
void attn_combine(const float* __restrict__ PO, const float* __restrict__ Pm,
                  const float* __restrict__ Pl,
                  hf* __restrict__ AVh, hf* __restrict__ AVl)
{
    const int t = blockIdx.x * 256 + threadIdx.x;
    const int bh = t >> 12;
    const int rem = t & 4095;
    const int row = rem >> 3;
    const int colg = (rem & 7) * 8;
    const int b = bh >> 4, h = bh & 15;

    const size_t r0 = (size_t)bh * CUR + row;
    const size_t r1 = (size_t)(64 + bh) * CUR + row;
    const float m0 = Pm[r0], m1 = Pm[r1];
    const float l0 = Pl[r0], l1 = Pl[r1];
    const float ms = fmaxf(m0, m1);
    const float f0 = __expf(m0 - ms), f1 = __expf(m1 - ms);
    const float inv = 1.f / (l0 * f0 + l1 * f1);

    const float* po0 = PO + r0 * 64 + colg;
    const float* po1 = PO + r1 * 64 + colg;
    hf* oh = AVh + (size_t)(row * BS + b) * DIMM + h * HD + colg;
    hf* ol = AVl + (size_t)(row * BS + b) * DIMM + h * HD + colg;

    #pragma unroll
    for (int c = 0; c < 8; c += 2) {
        float2 a = *(const float2*)&po0[c];
        float2 d = *(const float2*)&po1[c];
        float x = (a.x * f0 + d.x * f1) * inv;
        float y = (a.y * f0 + d.y * f1) * inv;
        store_split_h(&oh[c], &ol[c], x, y);
    }
}

// ---------------------------------------------------------------------------
// Launch
// ---------------------------------------------------------------------------
extern "C" void kernel_launch(void* const* d_in, const int* in_sizes, int n_in,
                              void* d_out, int out_size)
{
    const float* inputs  = (const float*)d_in[0];
    const float* pos_emb = (const float*)d_in[1];
    const float* full_in = (const float*)d_in[2];
    const float* u       = (const float*)d_in[3];
    const float* v       = (const float*)d_in[4];
    const float* W_kv    = (const float*)d_in[5];
    const float* b_kv    = (const float*)d_in[6];
    const float* W_q     = (const float*)d_in[7];
    const float* b_q     = (const float*)d_in[8];
    const float* W_pos   = (const float*)d_in[9];
    const float* b_pos   = (const float*)d_in[10];
    const float* W_proj  = (const float*)d_in[11];
    const float* b_proj  = (const float*)d_in[12];
    float* out = (float*)d_out;

    hf *FIh, *FIl, *INh, *INl, *PEh, *PEl, *Wkv, *Wq, *Wp, *Wpr,
       *KV, *Qu, *Qvh, *Qvl, *R, *AVh, *AVl, *C2;
    float *PO, *Pm, *Pl;
    cudaGetSymbolAddress((void**)&FIh, g_FIh);   cudaGetSymbolAddress((void**)&FIl, g_FIl);
    cudaGetSymbolAddress((void**)&INh, g_INh);   cudaGetSymbolAddress((void**)&INl, g_INl);
    cudaGetSymbolAddress((void**)&PEh, g_PEh);   cudaGetSymbolAddress((void**)&PEl, g_PEl);
    cudaGetSymbolAddress((void**)&Wkv, g_Wkv);   cudaGetSymbolAddress((void**)&Wq, g_Wq);
    cudaGetSymbolAddress((void**)&Wp, g_Wp);     cudaGetSymbolAddress((void**)&Wpr, g_Wpr);
    cudaGetSymbolAddress((void**)&KV, g_KV);
    cudaGetSymbolAddress((void**)&Qu, g_Qu);
    cudaGetSymbolAddress((void**)&Qvh, g_Qvh);   cudaGetSymbolAddress((void**)&Qvl, g_Qvl);
    cudaGetSymbolAddress((void**)&R, g_R);
    cudaGetSymbolAddress((void**)&AVh, g_AVh);   cudaGetSymbolAddress((void**)&AVl, g_AVl);
    cudaGetSymbolAddress((void**)&C2, g_C2h);
    cudaGetSymbolAddress((void**)&PO, g_PO);
    cudaGetSymbolAddress((void**)&Pm, g_Pm);
    cudaGetSymbolAddress((void**)&Pl, g_Pl);

    const int GSM = 4 * GSTAGE;     // 116736
    const int ASM = 2 * ASTAGE;     // 36864
    cudaFuncSetAttribute(gemm_mega, cudaFuncAttributeMaxDynamicSharedMemorySize, GSM);
    cudaFuncSetAttribute(attn_ca,   cudaFuncAttributeMaxDynamicSharedMemorySize, ASM);

    // 1. All conversions in one grid
    CT ct;
    ct.s[0] = full_in; ct.h[0] = FIh; ct.l[0] = FIl; ct.md[0] = 1;
    ct.s[1] = inputs;  ct.h[1] = INh; ct.l[1] = INl; ct.md[1] = 1;
    ct.s[2] = pos_emb; ct.h[2] = PEh; ct.l[2] = PEl; ct.md[2] = 1;
    ct.s[3] = W_kv;    ct.h[3] = Wkv; ct.l[3] = nullptr; ct.md[3] = 0;
    ct.s[4] = W_q;     ct.h[4] = Wq;  ct.l[4] = nullptr; ct.md[4] = 0;
    ct.s[5] = W_pos;   ct.h[5] = Wp;  ct.l[5] = nullptr; ct.md[5] = 0;
    ct.s[6] = W_proj;  ct.h[6] = Wpr; ct.l[6] = nullptr; ct.md[6] = 0;
    ct.end[0] = 4096;  ct.end[1] = 6144;  ct.end[2] = 7168;
    ct.end[3] = 9216;  ct.end[4] = 10240; ct.end[5] = 11264; ct.end[6] = 12288;
    cvt_mega<<<12288, 256>>>(ct);

    // 2. Mega GEMM {KV(single out), Q(Qu single + Qv split, x0.125), R(single)}
    GT3 ts;
    ts.t[0] = { FIh, FIl, Wkv, b_kv, nullptr, nullptr,
                nullptr, KV, nullptr, nullptr, nullptr, 2048, 1024, 16, 1 };
    ts.t[1] = { INh, INl, Wq, b_q, u, v,
                nullptr, Qu, nullptr, Qvh, Qvl, 1024, 1024, 8, 2 };
    ts.t[2] = { PEh, PEl, Wp, b_pos, nullptr, nullptr,
                nullptr, R, nullptr, nullptr, nullptr, 1024, 1024, 8, 1 };
    ts.end0 = 512; ts.end1 = 640;
    gemm_mega<<<704, 256, GSM>>>(ts);

    // 3. Position scores -> fp16
    pos_scores_bb<<<dim3(FULL / 64, CUR / 64, BS * NH), 128>>>(Qvh, Qvl, R, C2);

    // 4a. Fused attention, split-KV (partials)
    attn_ca<<<dim3(8, BS * NH), 256, ASM>>>(Qu, KV, C2, PO, Pm, Pl);

    // 4b. Combine partials -> AV (split fp16)
    attn_combine<<<(64 * 512 * 8) / 256, 256>>>(PO, Pm, Pl, AVh, AVl);

    // 5. out = AV @ W_proj + b_proj (fp32)
    GT3 tp;
    tp.t[0] = { AVh, AVl, Wpr, b_proj, nullptr, nullptr,
                out, nullptr, nullptr, nullptr, nullptr, 1024, 1024, 8, 0 };
    tp.t[1] = tp.t[0]; tp.t[2] = tp.t[0];
    tp.end0 = 128; tp.end1 = 128;
    gemm_mega<<<128, 256, GSM>>>(tp);
}